// round 13
// baseline (speedup 1.0000x reference)
#include <cuda_runtime.h>
#include <cuda_bf16.h>
#include <cstdint>

#define N_NODES  30000
#define N_EDGES  480000
#define N_GRAPHS 500
#define D1 78
#define D2 156
#define D3 312
#define SCAN_BLOCKS 30   // ceil(30000/1024)
#define GI_MAX 1888      // (118 tiles * 256 rows) / 16

// ---------------- scratch ----------------
__device__ int   g_cnt[N_NODES];
__device__ int   g_off[N_NODES + 1];
__device__ int   g_bsum[SCAN_BLOCKS];
__device__ int   g_csr[N_EDGES];
__device__ float g_dinv[N_NODES];
__device__ float g_y[(size_t)N_NODES * 320];            // f32 activations (padded strides)
__device__ uint2 g_s[(size_t)GI_MAX * 10 * 128];        // fragment-ordered split-bf16 A (max CH=10)
__device__ uint2 g_pooledS[N_GRAPHS * (D3 / 2)];
__device__ uint2 g_fc1S[N_GRAPHS * 512];
// weight fragments: uint4 per (chunk,ng,lane)
#define WF_OFF1 0
#define WF_OFF2 1600      // 5*10*32
#define WF_OFF3 4800      // +5*20*32
#define WF_OFFF1 17280    // +10*39*32
#define WF_OFFF2 99200    // +20*128*32
#define WF_TOTAL 131968   // +64*16*32
__device__ uint4 g_wfrag[WF_TOTAL];

// ---------------- bf16 split helpers ----------------
__device__ __forceinline__ uint32_t pack_bf16x2(float lo, float hi) {
    uint32_t r;
    asm("cvt.rn.bf16x2.f32 %0, %1, %2;" : "=r"(r) : "f"(hi), "f"(lo));
    return r;
}
__device__ __forceinline__ uint2 split2(float x, float y) {
    uint32_t s0 = pack_bf16x2(x, y);
    float r0 = x - __uint_as_float(s0 << 16);
    float r1 = y - __uint_as_float(s0 & 0xffff0000u);
    uint32_t s1 = pack_bf16x2(r0, r1);
    return make_uint2(s0, s1);
}

__device__ __forceinline__ void mma_bf16(float* c, const uint32_t* a, const uint32_t* b) {
    asm volatile(
        "mma.sync.aligned.m16n8k16.row.col.f32.bf16.bf16.f32 "
        "{%0,%1,%2,%3}, {%4,%5,%6,%7}, {%8,%9}, {%0,%1,%2,%3};\n"
        : "+f"(c[0]), "+f"(c[1]), "+f"(c[2]), "+f"(c[3])
        : "r"(a[0]), "r"(a[1]), "r"(a[2]), "r"(a[3]), "r"(b[0]), "r"(b[1]));
}

// fragment-ordered store: element (row m, pair c) -> A-fragment slot
template <int CH>
__device__ __forceinline__ void store_frag(uint2* __restrict__ outS, int m, int c, uint2 v) {
    int ch = c >> 3, cc = c & 7;
    int fl = ((m & 7) << 2) | (cc & 3);
    int reg = ((m >> 3) & 1) | ((cc & 4) >> 1);
    outS[((((size_t)(m >> 4)) * CH + ch) * 32 + fl) * 4 + reg] = v;
}

// ---------------- CSR build ----------------
__global__ void count_deg(const int2* __restrict__ dst2, int* __restrict__ cnt, int e2) {
    int i = blockIdx.x * blockDim.x + threadIdx.x;
    if (i < e2) {
        int2 d = dst2[i];
        atomicAdd(&cnt[d.x], 1);
        atomicAdd(&cnt[d.y], 1);
    }
}

__global__ void scan1(const int* __restrict__ cnt, int* __restrict__ off,
                      float* __restrict__ dinv, int* __restrict__ bsum) {
    __shared__ int sm[1024];
    int tid = threadIdx.x;
    int i = blockIdx.x * 1024 + tid;
    int c = (i < N_NODES) ? cnt[i] : 0;
    if (i < N_NODES) dinv[i] = rsqrtf((float)c + 1.0f);
    sm[tid] = c;
    __syncthreads();
    for (int d = 1; d < 1024; d <<= 1) {
        int t = (tid >= d) ? sm[tid - d] : 0;
        __syncthreads();
        sm[tid] += t;
        __syncthreads();
    }
    if (i < N_NODES) off[i] = sm[tid] - c;
    if (tid == 1023) bsum[blockIdx.x] = sm[1023];
}

__global__ void scan_add(int* __restrict__ off, const int* __restrict__ bsum) {
    __shared__ int pre[32];
    int tid = threadIdx.x;
    if (tid < 32) {
        int v = (tid < SCAN_BLOCKS) ? bsum[tid] : 0;
#pragma unroll
        for (int d = 1; d < 32; d <<= 1) {
            int t = __shfl_up_sync(0xffffffffu, v, d);
            if (tid >= d) v += t;
        }
        pre[tid] = v;
    }
    __syncthreads();
    int b = blockIdx.x;
    int add = (b == 0) ? 0 : pre[b - 1];
    int i = b * 1024 + tid;
    if (i < N_NODES && b > 0) off[i] += add;
    if (b == 0 && tid == 0) off[N_NODES] = N_EDGES;
}

// scatter edges (consumes cnt) + y0 = dinv*x (padded stride 40 float2)  [R10 proven]
__global__ void scatter_scale(const int* __restrict__ src, const int* __restrict__ dst,
                              const int* __restrict__ off, int* __restrict__ cnt,
                              int* __restrict__ csr, const float* __restrict__ dinv,
                              const float2* __restrict__ x2, float2* __restrict__ y0) {
    int t = blockIdx.x * blockDim.x + threadIdx.x;
    if (t < N_EDGES) {
        int d = dst[t];
        int pos = off[d] + atomicSub(&cnt[d], 1) - 1;
        csr[pos] = src[t];
    }
    const int DP = D1 / 2;
    int total = N_NODES * DP;
    int stride = gridDim.x * blockDim.x;
    for (int i = t; i < total; i += stride) {
        int node = i / DP;
        int f = i - node * DP;
        float2 v = x2[i];
        float di = dinv[node];
        y0[node * 40 + f] = make_float2(di * v.x, di * v.y);
    }
}

// ---------------- fused: zero cnt + weight -> fragment conversion ----------------
__global__ void conv_all(const float* __restrict__ W1, const float* __restrict__ W2,
                         const float* __restrict__ W3, const float* __restrict__ Wf1,
                         const float* __restrict__ Wf2, uint4* __restrict__ out,
                         int4* __restrict__ cnt4) {
    int zi = blockIdx.x * 256 + threadIdx.x;
    if (zi < N_NODES / 4) cnt4[zi] = make_int4(0, 0, 0, 0);

    int unit = blockIdx.x * 8 + (threadIdx.x >> 5);
    int lane = threadIdx.x & 31;
    const float* W; int K, N, NG, base, u;
    if (unit < 50)        { W = W1;  K = 78;   N = 78;   NG = 10;  base = WF_OFF1;  u = unit; }
    else if (unit < 150)  { W = W2;  K = 78;   N = 156;  NG = 20;  base = WF_OFF2;  u = unit - 50; }
    else if (unit < 540)  { W = W3;  K = 156;  N = 312;  NG = 39;  base = WF_OFF3;  u = unit - 150; }
    else if (unit < 3100) { W = Wf1; K = 312;  N = 1024; NG = 128; base = WF_OFFF1; u = unit - 540; }
    else if (unit < 4124) { W = Wf2; K = 1024; N = 128;  NG = 16;  base = WF_OFFF2; u = unit - 3100; }
    else return;
    int chunk = u / NG, ng = u % NG;
    int n = ng * 8 + (lane >> 2);
    int k0 = chunk * 16 + 2 * (lane & 3);
    float f[4];
#pragma unroll
    for (int j = 0; j < 4; j++) {
        int k = k0 + (j >> 1) * 8 + (j & 1);
        f[j] = (k < K && n < N) ? W[(size_t)k * N + n] : 0.f;
    }
    uint2 p0 = split2(f[0], f[1]);
    uint2 p1 = split2(f[2], f[3]);
    out[base + (size_t)u * 32 + lane] = make_uint4(p0.x, p1.x, p0.y, p1.y);
}

// ---------------- float4 aggregation -> fragment-ordered output ----------------
// a = dinv[i]*(y[i]+sum_e y[src]); y pre-scaled by dinv. Pads (c>=P) stored as zero.
template <int Q, int QSTRIDE, int P, int CH>
__global__ void aggregate_f4(const float4* __restrict__ y4, const int* __restrict__ off,
                             const int* __restrict__ csr, const float* __restrict__ dinv,
                             uint2* __restrict__ outS) {
    int node = blockIdx.x * blockDim.y + threadIdx.y;
    if (node >= N_NODES) return;
    int f = threadIdx.x;
    int beg = off[node], end = off[node + 1];
    const float4* yb = y4 + f;
    float4 acc = yb[(size_t)node * QSTRIDE];
    int e = beg;
    for (; e + 4 <= end; e += 4) {
        int s0 = csr[e], s1 = csr[e + 1], s2 = csr[e + 2], s3 = csr[e + 3];
        float4 v0 = yb[(size_t)s0 * QSTRIDE];
        float4 v1 = yb[(size_t)s1 * QSTRIDE];
        float4 v2 = yb[(size_t)s2 * QSTRIDE];
        float4 v3 = yb[(size_t)s3 * QSTRIDE];
        acc.x += (v0.x + v1.x) + (v2.x + v3.x);
        acc.y += (v0.y + v1.y) + (v2.y + v3.y);
        acc.z += (v0.z + v1.z) + (v2.z + v3.z);
        acc.w += (v0.w + v1.w) + (v2.w + v3.w);
    }
    for (; e < end; e++) {
        int s = csr[e];
        float4 v = yb[(size_t)s * QSTRIDE];
        acc.x += v.x; acc.y += v.y; acc.z += v.z; acc.w += v.w;
    }
    float di = dinv[node];
    uint2 v0 = make_uint2(0, 0), v1 = make_uint2(0, 0);
    if (2 * f < P) v0 = split2(di * acc.x, di * acc.y);
    if (2 * f + 1 < P) v1 = split2(di * acc.z, di * acc.w);
    store_frag<CH>(outS, node, 2 * f, v0);
    store_frag<CH>(outS, node, 2 * f + 1, v1);
}

// ---------------- node GEMM: A pre-fragmented in global, no SMEM, no barriers --------
// BM = 32*MI rows. acc in regs; 3 mma per (mi, ni) per chunk reproduce split product.
template <int MI, int CH, bool SCALE>
__global__ __launch_bounds__(256) void gemm_frag(const uint2* __restrict__ A2,
                                                 const uint4* __restrict__ BF, int NG,
                                                 const float* __restrict__ bias,
                                                 const float* __restrict__ rowscale,
                                                 float* __restrict__ Cf,
                                                 int M, int N, int strideC) {
    const uint4* A4 = reinterpret_cast<const uint4*>(A2);
    int tid = threadIdx.x;
    int warp = tid >> 5, lane = tid & 31;
    int g = lane >> 2, tig = lane & 3;
    int wm = warp >> 2, wn = warp & 3;
    int row0 = blockIdx.y * (32 * MI), col0 = blockIdx.x * 64;
    int gi0 = (row0 >> 4) + wm * MI;

    int ngBase = (col0 >> 3) + wn * 2;
    bool ngok0 = (ngBase < NG), ngok1 = (ngBase + 1 < NG);
    const uint4* BF0 = BF + (size_t)ngBase * 32 + lane;
    const uint4* BF1 = BF + (size_t)(ngBase + 1) * 32 + lane;

    float acc[MI][2][4];
#pragma unroll
    for (int a = 0; a < MI; a++)
#pragma unroll
        for (int b = 0; b < 2; b++)
#pragma unroll
            for (int c = 0; c < 4; c++) acc[a][b][c] = 0.f;

#pragma unroll
    for (int ch = 0; ch < CH; ch++) {
        uint4 bfr[2];
        size_t bo = (size_t)ch * NG * 32;
        bfr[0] = ngok0 ? BF0[bo] : make_uint4(0, 0, 0, 0);
        bfr[1] = ngok1 ? BF1[bo] : make_uint4(0, 0, 0, 0);
#pragma unroll
        for (int mi = 0; mi < MI; mi++) {
            size_t ao = ((((size_t)(gi0 + mi)) * CH + ch) * 32 + lane) * 2;
            uint4 q1 = A4[ao];
            uint4 q2 = A4[ao + 1];
            uint32_t ah[4] = {q1.x, q1.z, q2.x, q2.z};
            uint32_t al[4] = {q1.y, q1.w, q2.y, q2.w};
#pragma unroll
            for (int ni = 0; ni < 2; ni++) {
                uint32_t b0[2] = {bfr[ni].x, bfr[ni].y};
                uint32_t b1[2] = {bfr[ni].z, bfr[ni].w};
                mma_bf16(acc[mi][ni], ah, b0);
                mma_bf16(acc[mi][ni], al, b0);
                mma_bf16(acc[mi][ni], ah, b1);
            }
        }
    }

    // epilogue: bias + relu (+rowscale), f32 stores
#pragma unroll
    for (int mi = 0; mi < MI; mi++) {
        int r0 = row0 + wm * (MI * 16) + mi * 16 + g;
        int r1 = r0 + 8;
        float sc0 = 1.f, sc1 = 1.f;
        if (SCALE) {
            if (r0 < M) sc0 = rowscale[r0];
            if (r1 < M) sc1 = rowscale[r1];
        }
#pragma unroll
        for (int ni = 0; ni < 2; ni++) {
            int c0 = col0 + wn * 16 + ni * 8 + tig * 2;
            if (c0 < N) {
                float2 bia = *reinterpret_cast<const float2*>(&bias[c0]);
                if (r0 < M) {
                    float vx = fmaxf(acc[mi][ni][0] + bia.x, 0.f) * sc0;
                    float vy = fmaxf(acc[mi][ni][1] + bia.y, 0.f) * sc0;
                    *reinterpret_cast<float2*>(&Cf[(size_t)r0 * strideC + c0]) = make_float2(vx, vy);
                }
                if (r1 < M) {
                    float vx = fmaxf(acc[mi][ni][2] + bia.x, 0.f) * sc1;
                    float vy = fmaxf(acc[mi][ni][3] + bia.y, 0.f) * sc1;
                    *reinterpret_cast<float2*>(&Cf[(size_t)r1 * strideC + c0]) = make_float2(vx, vy);
                }
            }
        }
    }
}

// ---------------- mma.sync GEMM with SMEM loader (FC head only; R10 proven) ----------
template <int MI, bool RELU, bool SCALE, bool OSPLIT>
__global__ __launch_bounds__(256) void gemm_bf16s(const uint2* __restrict__ A, int KP,
                                                  const uint4* __restrict__ BF, int NG,
                                                  const float* __restrict__ bias,
                                                  const float* __restrict__ rowscale,
                                                  float* __restrict__ Cf,
                                                  uint2* __restrict__ Cs,
                                                  int M, int N, int K, int strideC) {
    constexpr int GI = 2 * MI;
    constexpr int BM = 16 * GI;
    constexpr int PLANE = GI * 128;
    __shared__ uint32_t ASw[2 * PLANE];
    const uint4* ASf4 = reinterpret_cast<const uint4*>(ASw);
    int tid = threadIdx.x;
    int warp = tid >> 5, lane = tid & 31;
    int g = lane >> 2, tig = lane & 3;
    int wm = warp >> 2, wn = warp & 3;
    int row0 = blockIdx.y * BM, col0 = blockIdx.x * 64;
    int chunks = (K + 15) >> 4;

    int li[MI], gbase[MI], colc[MI];
    bool rowok[MI];
#pragma unroll
    for (int j = 0; j < MI; j++) {
        int i = tid + j * 256;
        int m = i >> 3, c = i & 7;
        int gi = m >> 4;
        int fl = ((m & 7) << 2) | (c & 3);
        int reg = ((m >> 3) & 1) | ((c >> 2) << 1);
        li[j] = ((gi * 32 + fl) << 2) + reg;
        rowok[j] = (row0 + m) < M;
        gbase[j] = (row0 + m) * KP + c;
        colc[j] = c;
    }
    int ngBase = (col0 >> 3) + wn * 2;
    bool ngok0 = (ngBase < NG), ngok1 = (ngBase + 1 < NG);
    const uint4* BF0 = BF + (size_t)ngBase * 32 + lane;
    const uint4* BF1 = BF + (size_t)(ngBase + 1) * 32 + lane;

    float acc[MI][2][4];
#pragma unroll
    for (int a = 0; a < MI; a++)
#pragma unroll
        for (int b = 0; b < 2; b++)
#pragma unroll
            for (int c = 0; c < 4; c++) acc[a][b][c] = 0.f;

    for (int ch = 0; ch < chunks; ch++) {
        uint4 bfr[2];
        size_t bo = (size_t)ch * NG * 32;
        bfr[0] = ngok0 ? BF0[bo] : make_uint4(0, 0, 0, 0);
        bfr[1] = ngok1 ? BF1[bo] : make_uint4(0, 0, 0, 0);
        int gc = 8 * ch;
#pragma unroll
        for (int j = 0; j < MI; j++) {
            uint2 v = (rowok[j] && colc[j] + gc < KP) ? A[gbase[j] + gc] : make_uint2(0, 0);
            ASw[li[j]] = v.x;
            ASw[li[j] + PLANE] = v.y;
        }
        __syncthreads();
#pragma unroll
        for (int mi = 0; mi < MI; mi++) {
            int gi = wm * MI + mi;
            uint4 a0v = ASf4[gi * 32 + lane];
            uint4 a1v = ASf4[PLANE / 4 + gi * 32 + lane];
            const uint32_t* a0 = reinterpret_cast<const uint32_t*>(&a0v);
            const uint32_t* a1 = reinterpret_cast<const uint32_t*>(&a1v);
#pragma unroll
            for (int ni = 0; ni < 2; ni++) {
                uint32_t b0[2] = {bfr[ni].x, bfr[ni].y};
                uint32_t b1[2] = {bfr[ni].z, bfr[ni].w};
                mma_bf16(acc[mi][ni], a0, b0);
                mma_bf16(acc[mi][ni], a1, b0);
                mma_bf16(acc[mi][ni], a0, b1);
            }
        }
        __syncthreads();
    }

#pragma unroll
    for (int mi = 0; mi < MI; mi++) {
        int r0 = row0 + wm * (MI * 16) + mi * 16 + g;
        int r1 = r0 + 8;
        float sc0 = 1.f, sc1 = 1.f;
        if (SCALE) {
            if (r0 < M) sc0 = rowscale[r0];
            if (r1 < M) sc1 = rowscale[r1];
        }
#pragma unroll
        for (int ni = 0; ni < 2; ni++) {
            int c0 = col0 + wn * 16 + ni * 8 + tig * 2;
            if (c0 < N) {
                float2 bia = *reinterpret_cast<const float2*>(&bias[c0]);
                if (r0 < M) {
                    float vx = acc[mi][ni][0] + bia.x, vy = acc[mi][ni][1] + bia.y;
                    if (RELU) { vx = fmaxf(vx, 0.f); vy = fmaxf(vy, 0.f); }
                    if (SCALE) { vx *= sc0; vy *= sc0; }
                    if (OSPLIT) Cs[(size_t)r0 * (N >> 1) + (c0 >> 1)] = split2(vx, vy);
                    else *reinterpret_cast<float2*>(&Cf[(size_t)r0 * strideC + c0]) = make_float2(vx, vy);
                }
                if (r1 < M) {
                    float vx = acc[mi][ni][2] + bia.x, vy = acc[mi][ni][3] + bia.y;
                    if (RELU) { vx = fmaxf(vx, 0.f); vy = fmaxf(vy, 0.f); }
                    if (SCALE) { vx *= sc1; vy *= sc1; }
                    if (OSPLIT) Cs[(size_t)r1 * (N >> 1) + (c0 >> 1)] = split2(vx, vy);
                    else *reinterpret_cast<float2*>(&Cf[(size_t)r1 * strideC + c0]) = make_float2(vx, vy);
                }
            }
        }
    }
}

// ---------------- max pool (h3 rows padded to 320 floats = 80 quads) ----------------
__global__ void pool_kernel(const float4* __restrict__ h4, const int* __restrict__ batch,
                            uint2* __restrict__ pooledS) {
    __shared__ int sb[2];
    __shared__ float4 red[4][80];
    int lane = threadIdx.x, ty = threadIdx.y, gr = blockIdx.x;
    if (ty == 0 && lane < 2) {
        int target = gr + lane, lo = 0, hi = N_NODES;
        while (lo < hi) { int mid = (lo + hi) >> 1; if (batch[mid] < target) lo = mid + 1; else hi = mid; }
        sb[lane] = lo;
    }
    __syncthreads();
    int beg = sb[0], end = sb[1];
    const int DQ = D3 / 4;
    float4 m = make_float4(0.f, 0.f, 0.f, 0.f);
    if (lane < DQ) {
        for (int node = beg + ty; node < end; node += 4) {
            float4 v = h4[(size_t)node * 80 + lane];
            m.x = fmaxf(m.x, v.x); m.y = fmaxf(m.y, v.y);
            m.z = fmaxf(m.z, v.z); m.w = fmaxf(m.w, v.w);
        }
    }
    red[ty][lane] = m;
    __syncthreads();
    if (ty == 0 && lane < DQ) {
        float4 a = red[0][lane], b = red[1][lane], c = red[2][lane], d = red[3][lane];
        float4 r;
        r.x = fmaxf(fmaxf(a.x, b.x), fmaxf(c.x, d.x));
        r.y = fmaxf(fmaxf(a.y, b.y), fmaxf(c.y, d.y));
        r.z = fmaxf(fmaxf(a.z, b.z), fmaxf(c.z, d.z));
        r.w = fmaxf(fmaxf(a.w, b.w), fmaxf(c.w, d.w));
        pooledS[(size_t)gr * (D3 / 2) + 2 * lane]     = split2(r.x, r.y);
        pooledS[(size_t)gr * (D3 / 2) + 2 * lane + 1] = split2(r.z, r.w);
    }
}

// ---------------- launch ----------------
extern "C" void kernel_launch(void* const* d_in, const int* in_sizes, int n_in,
                              void* d_out, int out_size) {
    const float* x     = (const float*)d_in[0];
    const int*   ei    = (const int*)d_in[1];
    const int*   batch = (const int*)d_in[2];
    const float* W1 = (const float*)d_in[3];  const float* b1  = (const float*)d_in[4];
    const float* W2 = (const float*)d_in[5];  const float* b2  = (const float*)d_in[6];
    const float* W3 = (const float*)d_in[7];  const float* b3  = (const float*)d_in[8];
    const float* Wf1 = (const float*)d_in[9]; const float* bf1 = (const float*)d_in[10];
    const float* Wf2 = (const float*)d_in[11];const float* bf2 = (const float*)d_in[12];
    float* out = (float*)d_out;

    const int* src = ei;
    const int* dst = ei + N_EDGES;

    int *cnt, *off, *csr, *bsum;
    float *dinv, *y;
    uint2 *s, *pooledS, *fc1S;
    uint4 *wf;
    cudaGetSymbolAddress((void**)&cnt, g_cnt);
    cudaGetSymbolAddress((void**)&off, g_off);
    cudaGetSymbolAddress((void**)&csr, g_csr);
    cudaGetSymbolAddress((void**)&bsum, g_bsum);
    cudaGetSymbolAddress((void**)&dinv, g_dinv);
    cudaGetSymbolAddress((void**)&y, g_y);
    cudaGetSymbolAddress((void**)&s, g_s);
    cudaGetSymbolAddress((void**)&pooledS, g_pooledS);
    cudaGetSymbolAddress((void**)&fc1S, g_fc1S);
    cudaGetSymbolAddress((void**)&wf, g_wfrag);

    // ---- fused zero(cnt) + weight fragment conversion ----
    conv_all<<<(4124 + 7) / 8, 256>>>(W1, W2, W3, Wf1, Wf2, wf, (int4*)cnt);

    // ---- CSR build + y0 = dinv*x (stride 80 floats) ----
    count_deg<<<(N_EDGES / 2 + 255) / 256, 256>>>((const int2*)dst, cnt, N_EDGES / 2);
    scan1<<<SCAN_BLOCKS, 1024>>>(cnt, off, dinv, bsum);
    scan_add<<<SCAN_BLOCKS, 1024>>>(off, bsum);
    scatter_scale<<<(N_EDGES + 255) / 256, 256>>>(src, dst, off, cnt, csr, dinv,
                                                  (const float2*)x, (float2*)y);

    const int RB256 = (N_NODES + 255) / 256;  // 118

    // ---- layer 1: y1 = dinv*relu(agg(y0)@W1+b1), stride 80 ----
    aggregate_f4<20, 20, 39, 5><<<(N_NODES + 11) / 12, dim3(20, 12)>>>(
        (const float4*)y, off, csr, dinv, s);
    gemm_frag<8, 5, true><<<dim3(2, RB256), 256>>>(
        s, wf + WF_OFF1, 10, b1, dinv, y, N_NODES, D1, 80);

    // ---- layer 2: y2 stride 160 ----
    aggregate_f4<20, 20, 39, 5><<<(N_NODES + 11) / 12, dim3(20, 12)>>>(
        (const float4*)y, off, csr, dinv, s);
    gemm_frag<8, 5, true><<<dim3(3, RB256), 256>>>(
        s, wf + WF_OFF2, 20, b2, dinv, y, N_NODES, D2, 160);

    // ---- layer 3: h3 stride 320 (unscaled, feeds pooling) ----
    aggregate_f4<40, 40, 78, 10><<<(N_NODES + 5) / 6, dim3(40, 6)>>>(
        (const float4*)y, off, csr, dinv, s);
    gemm_frag<8, 10, false><<<dim3(5, RB256), 256>>>(
        s, wf + WF_OFF3, 39, b3, nullptr, y, N_NODES, D3, 320);

    // ---- pool ----
    pool_kernel<<<N_GRAPHS, dim3(80, 4)>>>((const float4*)y, batch, pooledS);

    // ---- FC head (R10 proven SMEM path; MI=4 keeps grids wide) ----
    gemm_bf16s<4, true, false, true><<<dim3(16, (N_GRAPHS + 127) / 128), 256>>>(
        pooledS, D3 / 2, wf + WF_OFFF1, 128, bf1, nullptr, nullptr, fc1S, N_GRAPHS, 1024, D3, 0);
    gemm_bf16s<4, false, false, false><<<dim3(2, (N_GRAPHS + 127) / 128), 256>>>(
        fc1S, 512, wf + WF_OFFF2, 16, bf2, nullptr, out, nullptr, N_GRAPHS, 128, 1024, 128);
}

// round 14
// speedup vs baseline: 1.3170x; 1.3170x over previous
#include <cuda_runtime.h>
#include <cuda_bf16.h>
#include <cuda_fp16.h>
#include <cstdint>

#define N_NODES  30000
#define N_EDGES  480000
#define N_GRAPHS 500
#define D1 78
#define D2 156
#define D3 312
#define SCAN_BLOCKS 30   // ceil(30000/1024)

// ---------------- scratch ----------------
__device__ int   g_cnt[N_NODES];
__device__ int   g_off[N_NODES + 1];
__device__ int   g_bsum[SCAN_BLOCKS];
__device__ int   g_csr[N_EDGES];
__device__ float g_dinv[N_NODES];
__device__ uint2 g_yh[(size_t)N_NODES * 80];         // fp16 activations (half2-packed, padded strides)
__device__ uint2 g_s[(size_t)N_NODES * (D2 / 2)];    // split-bf16 packed GEMM input (fp32-accurate)
__device__ uint2 g_pooledS[N_GRAPHS * (D3 / 2)];
__device__ uint2 g_fc1S[N_GRAPHS * 512];
// weight fragments: uint4 per (chunk,ng,lane)
#define WF_OFF1 0
#define WF_OFF2 1600      // 5*10*32
#define WF_OFF3 4800      // +5*20*32
#define WF_OFFF1 17280    // +10*39*32
#define WF_OFFF2 99200    // +20*128*32
#define WF_TOTAL 131968   // +64*16*32
__device__ uint4 g_wfrag[WF_TOTAL];

// ---------------- helpers ----------------
__device__ __forceinline__ uint32_t pack_bf16x2(float lo, float hi) {
    uint32_t r;
    asm("cvt.rn.bf16x2.f32 %0, %1, %2;" : "=r"(r) : "f"(hi), "f"(lo));
    return r;
}
__device__ __forceinline__ uint2 split2(float x, float y) {
    uint32_t s0 = pack_bf16x2(x, y);
    float r0 = x - __uint_as_float(s0 << 16);
    float r1 = y - __uint_as_float(s0 & 0xffff0000u);
    uint32_t s1 = pack_bf16x2(r0, r1);
    return make_uint2(s0, s1);
}
__device__ __forceinline__ uint32_t pack_h2(float a, float b) {
    __half2 h = __floats2half2_rn(a, b);
    return *reinterpret_cast<uint32_t*>(&h);
}
__device__ __forceinline__ float4 h2x2_to_f4(uint2 u) {
    float2 a = __half22float2(*reinterpret_cast<__half2*>(&u.x));
    float2 b = __half22float2(*reinterpret_cast<__half2*>(&u.y));
    return make_float4(a.x, a.y, b.x, b.y);
}

__device__ __forceinline__ void mma_bf16(float* c, const uint32_t* a, const uint32_t* b) {
    asm volatile(
        "mma.sync.aligned.m16n8k16.row.col.f32.bf16.bf16.f32 "
        "{%0,%1,%2,%3}, {%4,%5,%6,%7}, {%8,%9}, {%0,%1,%2,%3};\n"
        : "+f"(c[0]), "+f"(c[1]), "+f"(c[2]), "+f"(c[3])
        : "r"(a[0]), "r"(a[1]), "r"(a[2]), "r"(a[3]), "r"(b[0]), "r"(b[1]));
}

// ---------------- CSR build ----------------
__global__ void count_deg(const int2* __restrict__ dst2, int* __restrict__ cnt, int e2) {
    int i = blockIdx.x * blockDim.x + threadIdx.x;
    if (i < e2) {
        int2 d = dst2[i];
        atomicAdd(&cnt[d.x], 1);
        atomicAdd(&cnt[d.y], 1);
    }
}

__global__ void scan1(const int* __restrict__ cnt, int* __restrict__ off,
                      float* __restrict__ dinv, int* __restrict__ bsum) {
    __shared__ int sm[1024];
    int tid = threadIdx.x;
    int i = blockIdx.x * 1024 + tid;
    int c = (i < N_NODES) ? cnt[i] : 0;
    if (i < N_NODES) dinv[i] = rsqrtf((float)c + 1.0f);
    sm[tid] = c;
    __syncthreads();
    for (int d = 1; d < 1024; d <<= 1) {
        int t = (tid >= d) ? sm[tid - d] : 0;
        __syncthreads();
        sm[tid] += t;
        __syncthreads();
    }
    if (i < N_NODES) off[i] = sm[tid] - c;
    if (tid == 1023) bsum[blockIdx.x] = sm[1023];
}

__global__ void scan_add(int* __restrict__ off, const int* __restrict__ bsum) {
    __shared__ int pre[32];
    int tid = threadIdx.x;
    if (tid < 32) {
        int v = (tid < SCAN_BLOCKS) ? bsum[tid] : 0;
#pragma unroll
        for (int d = 1; d < 32; d <<= 1) {
            int t = __shfl_up_sync(0xffffffffu, v, d);
            if (tid >= d) v += t;
        }
        pre[tid] = v;
    }
    __syncthreads();
    int b = blockIdx.x;
    int add = (b == 0) ? 0 : pre[b - 1];
    int i = b * 1024 + tid;
    if (i < N_NODES && b > 0) off[i] += add;
    if (b == 0 && tid == 0) off[N_NODES] = N_EDGES;
}

// scatter edges (consumes cnt) + y0 = fp16(dinv * x), row stride 40 uint (80 feats)
__global__ void scatter_scale(const int* __restrict__ src, const int* __restrict__ dst,
                              const int* __restrict__ off, int* __restrict__ cnt,
                              int* __restrict__ csr, const float* __restrict__ dinv,
                              const float2* __restrict__ x2, uint32_t* __restrict__ yh) {
    int t = blockIdx.x * blockDim.x + threadIdx.x;
    if (t < N_EDGES) {
        int d = dst[t];
        int pos = off[d] + atomicSub(&cnt[d], 1) - 1;
        csr[pos] = src[t];
    }
    const int DP = D1 / 2;  // 39 pairs
    int total = N_NODES * DP;
    int stride = gridDim.x * blockDim.x;
    for (int i = t; i < total; i += stride) {
        int node = i / DP;
        int f = i - node * DP;
        float2 v = x2[i];
        float di = dinv[node];
        yh[node * 40 + f] = pack_h2(di * v.x, di * v.y);
    }
}

// ---------------- fused: zero cnt + weight -> fragment conversion ----------------
__global__ void conv_all(const float* __restrict__ W1, const float* __restrict__ W2,
                         const float* __restrict__ W3, const float* __restrict__ Wf1,
                         const float* __restrict__ Wf2, uint4* __restrict__ out,
                         int4* __restrict__ cnt4) {
    int zi = blockIdx.x * 256 + threadIdx.x;
    if (zi < N_NODES / 4) cnt4[zi] = make_int4(0, 0, 0, 0);

    int unit = blockIdx.x * 8 + (threadIdx.x >> 5);
    int lane = threadIdx.x & 31;
    const float* W; int K, N, NG, base, u;
    if (unit < 50)        { W = W1;  K = 78;   N = 78;   NG = 10;  base = WF_OFF1;  u = unit; }
    else if (unit < 150)  { W = W2;  K = 78;   N = 156;  NG = 20;  base = WF_OFF2;  u = unit - 50; }
    else if (unit < 540)  { W = W3;  K = 156;  N = 312;  NG = 39;  base = WF_OFF3;  u = unit - 150; }
    else if (unit < 3100) { W = Wf1; K = 312;  N = 1024; NG = 128; base = WF_OFFF1; u = unit - 540; }
    else if (unit < 4124) { W = Wf2; K = 1024; N = 128;  NG = 16;  base = WF_OFFF2; u = unit - 3100; }
    else return;
    int chunk = u / NG, ng = u % NG;
    int n = ng * 8 + (lane >> 2);
    int k0 = chunk * 16 + 2 * (lane & 3);
    float f[4];
#pragma unroll
    for (int j = 0; j < 4; j++) {
        int k = k0 + (j >> 1) * 8 + (j & 1);
        f[j] = (k < K && n < N) ? W[(size_t)k * N + n] : 0.f;
    }
    uint2 p0 = split2(f[0], f[1]);
    uint2 p1 = split2(f[2], f[3]);
    out[base + (size_t)u * 32 + lane] = make_uint4(p0.x, p1.x, p0.y, p1.y);
}

// ---------------- aggregation over fp16 y, fp32 accumulate, split-bf16 out ----------
// a = dinv[i]*(y[i]+sum_e y[src]); y pre-scaled by dinv. uint2 = 4 features.
template <int Q, int QS, int P>
__global__ void aggregate_h2(const uint2* __restrict__ y2, const int* __restrict__ off,
                             const int* __restrict__ csr, const float* __restrict__ dinv,
                             uint2* __restrict__ outS) {
    int node = blockIdx.x * blockDim.y + threadIdx.y;
    if (node >= N_NODES) return;
    int f = threadIdx.x;
    int beg = off[node], end = off[node + 1];
    const uint2* yb = y2 + f;
    float4 acc = h2x2_to_f4(yb[(size_t)node * QS]);
    int e = beg;
    for (; e + 4 <= end; e += 4) {
        int s0 = csr[e], s1 = csr[e + 1], s2 = csr[e + 2], s3 = csr[e + 3];
        float4 v0 = h2x2_to_f4(yb[(size_t)s0 * QS]);
        float4 v1 = h2x2_to_f4(yb[(size_t)s1 * QS]);
        float4 v2 = h2x2_to_f4(yb[(size_t)s2 * QS]);
        float4 v3 = h2x2_to_f4(yb[(size_t)s3 * QS]);
        acc.x += (v0.x + v1.x) + (v2.x + v3.x);
        acc.y += (v0.y + v1.y) + (v2.y + v3.y);
        acc.z += (v0.z + v1.z) + (v2.z + v3.z);
        acc.w += (v0.w + v1.w) + (v2.w + v3.w);
    }
    for (; e < end; e++) {
        int s = csr[e];
        float4 v = h2x2_to_f4(yb[(size_t)s * QS]);
        acc.x += v.x; acc.y += v.y; acc.z += v.z; acc.w += v.w;
    }
    float di = dinv[node];
    if (2 * f < P)
        outS[(size_t)node * P + 2 * f] = split2(di * acc.x, di * acc.y);
    if (2 * f + 1 < P)
        outS[(size_t)node * P + 2 * f + 1] = split2(di * acc.z, di * acc.w);
}

// ---------------- bf16-split tensor GEMM (R10 proven), OMODE output --------------
// OMODE: 0 = f32 float2, 1 = split-bf16 uint2, 2 = fp16 half2 (strideC in uint units)
template <int MI, bool RELU, bool SCALE, int OMODE>
__global__ __launch_bounds__(256) void gemm_bf16s(const uint2* __restrict__ A, int KP,
                                                  const uint4* __restrict__ BF, int NG,
                                                  const float* __restrict__ bias,
                                                  const float* __restrict__ rowscale,
                                                  float* __restrict__ Cf,
                                                  uint2* __restrict__ Cs,
                                                  uint32_t* __restrict__ Ch,
                                                  int M, int N, int K, int strideC) {
    constexpr int GI = 2 * MI;
    constexpr int BM = 16 * GI;
    constexpr int PLANE = GI * 128;
    __shared__ uint32_t ASw[2 * PLANE];
    const uint4* ASf4 = reinterpret_cast<const uint4*>(ASw);
    int tid = threadIdx.x;
    int warp = tid >> 5, lane = tid & 31;
    int g = lane >> 2, tig = lane & 3;
    int wm = warp >> 2, wn = warp & 3;
    int row0 = blockIdx.y * BM, col0 = blockIdx.x * 64;
    int chunks = (K + 15) >> 4;

    int li[MI], gbase[MI], colc[MI];
    bool rowok[MI];
#pragma unroll
    for (int j = 0; j < MI; j++) {
        int i = tid + j * 256;
        int m = i >> 3, c = i & 7;
        int gi = m >> 4;
        int fl = ((m & 7) << 2) | (c & 3);
        int reg = ((m >> 3) & 1) | ((c >> 2) << 1);
        li[j] = ((gi * 32 + fl) << 2) + reg;
        rowok[j] = (row0 + m) < M;
        gbase[j] = (row0 + m) * KP + c;
        colc[j] = c;
    }
    int ngBase = (col0 >> 3) + wn * 2;
    bool ngok0 = (ngBase < NG), ngok1 = (ngBase + 1 < NG);
    const uint4* BF0 = BF + (size_t)ngBase * 32 + lane;
    const uint4* BF1 = BF + (size_t)(ngBase + 1) * 32 + lane;

    float acc[MI][2][4];
#pragma unroll
    for (int a = 0; a < MI; a++)
#pragma unroll
        for (int b = 0; b < 2; b++)
#pragma unroll
            for (int c = 0; c < 4; c++) acc[a][b][c] = 0.f;

    for (int ch = 0; ch < chunks; ch++) {
        uint4 bfr[2];
        size_t bo = (size_t)ch * NG * 32;
        bfr[0] = ngok0 ? BF0[bo] : make_uint4(0, 0, 0, 0);
        bfr[1] = ngok1 ? BF1[bo] : make_uint4(0, 0, 0, 0);
        int gc = 8 * ch;
#pragma unroll
        for (int j = 0; j < MI; j++) {
            uint2 v = (rowok[j] && colc[j] + gc < KP) ? A[gbase[j] + gc] : make_uint2(0, 0);
            ASw[li[j]] = v.x;
            ASw[li[j] + PLANE] = v.y;
        }
        __syncthreads();

#pragma unroll
        for (int mi = 0; mi < MI; mi++) {
            int gi = wm * MI + mi;
            uint4 a0v = ASf4[gi * 32 + lane];
            uint4 a1v = ASf4[PLANE / 4 + gi * 32 + lane];
            const uint32_t* a0 = reinterpret_cast<const uint32_t*>(&a0v);
            const uint32_t* a1 = reinterpret_cast<const uint32_t*>(&a1v);
#pragma unroll
            for (int ni = 0; ni < 2; ni++) {
                uint32_t b0[2] = {bfr[ni].x, bfr[ni].y};
                uint32_t b1[2] = {bfr[ni].z, bfr[ni].w};
                mma_bf16(acc[mi][ni], a0, b0);
                mma_bf16(acc[mi][ni], a1, b0);
                mma_bf16(acc[mi][ni], a0, b1);
            }
        }
        __syncthreads();
    }

#pragma unroll
    for (int mi = 0; mi < MI; mi++) {
        int r0 = row0 + wm * (MI * 16) + mi * 16 + g;
        int r1 = r0 + 8;
        float sc0 = 1.f, sc1 = 1.f;
        if (SCALE) {
            if (r0 < M) sc0 = rowscale[r0];
            if (r1 < M) sc1 = rowscale[r1];
        }
#pragma unroll
        for (int ni = 0; ni < 2; ni++) {
            int c0 = col0 + wn * 16 + ni * 8 + tig * 2;
            if (c0 < N) {
                float2 bia = *reinterpret_cast<const float2*>(&bias[c0]);
                if (r0 < M) {
                    float vx = acc[mi][ni][0] + bia.x, vy = acc[mi][ni][1] + bia.y;
                    if (RELU) { vx = fmaxf(vx, 0.f); vy = fmaxf(vy, 0.f); }
                    if (SCALE) { vx *= sc0; vy *= sc0; }
                    if (OMODE == 1) Cs[(size_t)r0 * (N >> 1) + (c0 >> 1)] = split2(vx, vy);
                    else if (OMODE == 2) Ch[(size_t)r0 * strideC + (c0 >> 1)] = pack_h2(vx, vy);
                    else *reinterpret_cast<float2*>(&Cf[(size_t)r0 * strideC + c0]) = make_float2(vx, vy);
                }
                if (r1 < M) {
                    float vx = acc[mi][ni][2] + bia.x, vy = acc[mi][ni][3] + bia.y;
                    if (RELU) { vx = fmaxf(vx, 0.f); vy = fmaxf(vy, 0.f); }
                    if (SCALE) { vx *= sc1; vy *= sc1; }
                    if (OMODE == 1) Cs[(size_t)r1 * (N >> 1) + (c0 >> 1)] = split2(vx, vy);
                    else if (OMODE == 2) Ch[(size_t)r1 * strideC + (c0 >> 1)] = pack_h2(vx, vy);
                    else *reinterpret_cast<float2*>(&Cf[(size_t)r1 * strideC + c0]) = make_float2(vx, vy);
                }
            }
        }
    }
}

// ---------------- max pool over fp16 h3 (row stride 80 uint2 = 320 feats) -----------
__global__ void pool_kernel(const uint2* __restrict__ h2v, const int* __restrict__ batch,
                            uint2* __restrict__ pooledS) {
    __shared__ int sb[2];
    __shared__ float4 red[4][80];
    int lane = threadIdx.x, ty = threadIdx.y, gr = blockIdx.x;
    if (ty == 0 && lane < 2) {
        int target = gr + lane, lo = 0, hi = N_NODES;
        while (lo < hi) { int mid = (lo + hi) >> 1; if (batch[mid] < target) lo = mid + 1; else hi = mid; }
        sb[lane] = lo;
    }
    __syncthreads();
    int beg = sb[0], end = sb[1];
    const int DQ = D3 / 4;  // 78 uint2 lanes
    float4 m = make_float4(0.f, 0.f, 0.f, 0.f);
    if (lane < DQ) {
        for (int node = beg + ty; node < end; node += 4) {
            float4 v = h2x2_to_f4(h2v[(size_t)node * 80 + lane]);
            m.x = fmaxf(m.x, v.x); m.y = fmaxf(m.y, v.y);
            m.z = fmaxf(m.z, v.z); m.w = fmaxf(m.w, v.w);
        }
    }
    red[ty][lane] = m;
    __syncthreads();
    if (ty == 0 && lane < DQ) {
        float4 a = red[0][lane], b = red[1][lane], c = red[2][lane], d = red[3][lane];
        float4 r;
        r.x = fmaxf(fmaxf(a.x, b.x), fmaxf(c.x, d.x));
        r.y = fmaxf(fmaxf(a.y, b.y), fmaxf(c.y, d.y));
        r.z = fmaxf(fmaxf(a.z, b.z), fmaxf(c.z, d.z));
        r.w = fmaxf(fmaxf(a.w, b.w), fmaxf(c.w, d.w));
        pooledS[(size_t)gr * (D3 / 2) + 2 * lane]     = split2(r.x, r.y);
        pooledS[(size_t)gr * (D3 / 2) + 2 * lane + 1] = split2(r.z, r.w);
    }
}

// ---------------- launch ----------------
extern "C" void kernel_launch(void* const* d_in, const int* in_sizes, int n_in,
                              void* d_out, int out_size) {
    const float* x     = (const float*)d_in[0];
    const int*   ei    = (const int*)d_in[1];
    const int*   batch = (const int*)d_in[2];
    const float* W1 = (const float*)d_in[3];  const float* b1  = (const float*)d_in[4];
    const float* W2 = (const float*)d_in[5];  const float* b2  = (const float*)d_in[6];
    const float* W3 = (const float*)d_in[7];  const float* b3  = (const float*)d_in[8];
    const float* Wf1 = (const float*)d_in[9]; const float* bf1 = (const float*)d_in[10];
    const float* Wf2 = (const float*)d_in[11];const float* bf2 = (const float*)d_in[12];
    float* out = (float*)d_out;

    const int* src = ei;
    const int* dst = ei + N_EDGES;

    int *cnt, *off, *csr, *bsum;
    float *dinv;
    uint2 *yh, *s, *pooledS, *fc1S;
    uint4 *wf;
    cudaGetSymbolAddress((void**)&cnt, g_cnt);
    cudaGetSymbolAddress((void**)&off, g_off);
    cudaGetSymbolAddress((void**)&csr, g_csr);
    cudaGetSymbolAddress((void**)&bsum, g_bsum);
    cudaGetSymbolAddress((void**)&dinv, g_dinv);
    cudaGetSymbolAddress((void**)&yh, g_yh);
    cudaGetSymbolAddress((void**)&s, g_s);
    cudaGetSymbolAddress((void**)&pooledS, g_pooledS);
    cudaGetSymbolAddress((void**)&fc1S, g_fc1S);
    cudaGetSymbolAddress((void**)&wf, g_wfrag);
    uint32_t* yhu = (uint32_t*)yh;

    // ---- fused zero(cnt) + weight fragment conversion ----
    conv_all<<<(4124 + 7) / 8, 256>>>(W1, W2, W3, Wf1, Wf2, wf, (int4*)cnt);

    // ---- CSR build + y0 = fp16(dinv*x), stride 40 uint ----
    count_deg<<<(N_EDGES / 2 + 255) / 256, 256>>>((const int2*)dst, cnt, N_EDGES / 2);
    scan1<<<SCAN_BLOCKS, 1024>>>(cnt, off, dinv, bsum);
    scan_add<<<SCAN_BLOCKS, 1024>>>(off, bsum);
    scatter_scale<<<(N_EDGES + 255) / 256, 256>>>(src, dst, off, cnt, csr, dinv,
                                                  (const float2*)x, yhu);

    const int RB256 = (N_NODES + 255) / 256;  // 118

    // ---- layer 1: y1 = fp16(dinv*relu(agg(y0)@W1+b1)), stride 40 uint ----
    aggregate_h2<20, 20, 39><<<(N_NODES + 11) / 12, dim3(20, 12)>>>(yh, off, csr, dinv, s);
    gemm_bf16s<8, true, true, 2><<<dim3(2, RB256), 256>>>(
        s, D1 / 2, wf + WF_OFF1, 10, b1, dinv, nullptr, nullptr, yhu, N_NODES, D1, D1, 40);

    // ---- layer 2: y2 stride 80 uint ----
    aggregate_h2<20, 20, 39><<<(N_NODES + 11) / 12, dim3(20, 12)>>>(yh, off, csr, dinv, s);
    gemm_bf16s<8, true, true, 2><<<dim3(3, RB256), 256>>>(
        s, D1 / 2, wf + WF_OFF2, 20, b2, dinv, nullptr, nullptr, yhu, N_NODES, D2, D1, 80);

    // ---- layer 3: h3 stride 160 uint (unscaled, feeds pooling) ----
    aggregate_h2<40, 40, 78><<<(N_NODES + 5) / 6, dim3(40, 6)>>>(yh, off, csr, dinv, s);
    gemm_bf16s<8, true, false, 2><<<dim3(5, RB256), 256>>>(
        s, D2 / 2, wf + WF_OFF3, 39, b3, nullptr, nullptr, nullptr, yhu, N_NODES, D3, D2, 160);

    // ---- pool ----
    pool_kernel<<<N_GRAPHS, dim3(80, 4)>>>(yh, batch, pooledS);

    // ---- FC head (fp32-split path, unchanged) ----
    gemm_bf16s<4, true, false, 1><<<dim3(16, (N_GRAPHS + 127) / 128), 256>>>(
        pooledS, D3 / 2, wf + WF_OFFF1, 128, bf1, nullptr, nullptr, fc1S, nullptr,
        N_GRAPHS, 1024, D3, 0);
    gemm_bf16s<4, false, false, 0><<<dim3(2, (N_GRAPHS + 127) / 128), 256>>>(
        fc1S, 512, wf + WF_OFFF2, 16, bf2, nullptr, out, nullptr, nullptr,
        N_GRAPHS, 128, 1024, 128);
}

// round 15
// speedup vs baseline: 1.4269x; 1.0835x over previous
#include <cuda_runtime.h>
#include <cuda_bf16.h>
#include <cuda_fp16.h>
#include <cstdint>

#define N_NODES  30000
#define N_EDGES  480000
#define N_GRAPHS 500
#define D1 78
#define D2 156
#define D3 312
#define SCAN_BLOCKS 30   // ceil(30000/1024)

// ---------------- scratch ----------------
__device__ int   g_cnt[N_NODES];
__device__ int   g_off[N_NODES + 1];
__device__ int   g_bsum[SCAN_BLOCKS];
__device__ int   g_csr[N_EDGES];
__device__ float g_dinv[N_NODES];
__device__ uint2 g_yh[(size_t)N_NODES * 80];         // fp16 activations (half2-packed, padded)
__device__ uint32_t g_sA[(size_t)N_NODES * D1];      // fp16 GEMM A (pairs; max 78/row)
__device__ uint2 g_pooledS[N_GRAPHS * (D3 / 2)];
__device__ uint2 g_fc1S[N_GRAPHS * 512];
// weight fragments: uint4 per (chunk,ng,lane); node layers = split-fp16, FC = split-bf16
#define WF_OFF1 0
#define WF_OFF2 1600      // 5*10*32
#define WF_OFF3 4800      // +5*20*32
#define WF_OFFF1 17280    // +10*39*32
#define WF_OFFF2 99200    // +20*128*32
#define WF_TOTAL 131968   // +64*16*32
__device__ uint4 g_wfrag[WF_TOTAL];

// ---------------- helpers ----------------
__device__ __forceinline__ uint32_t pack_bf16x2(float lo, float hi) {
    uint32_t r;
    asm("cvt.rn.bf16x2.f32 %0, %1, %2;" : "=r"(r) : "f"(hi), "f"(lo));
    return r;
}
__device__ __forceinline__ uint2 split2(float x, float y) {      // split-bf16 (FC path)
    uint32_t s0 = pack_bf16x2(x, y);
    float r0 = x - __uint_as_float(s0 << 16);
    float r1 = y - __uint_as_float(s0 & 0xffff0000u);
    uint32_t s1 = pack_bf16x2(r0, r1);
    return make_uint2(s0, s1);
}
__device__ __forceinline__ uint32_t pack_h2(float a, float b) {
    __half2 h = __floats2half2_rn(a, b);
    return *reinterpret_cast<uint32_t*>(&h);
}
__device__ __forceinline__ uint2 split2h(float x, float y) {     // split-fp16 (node W path)
    uint32_t s0 = pack_h2(x, y);
    float2 f = __half22float2(*reinterpret_cast<__half2*>(&s0));
    uint32_t s1 = pack_h2(x - f.x, y - f.y);
    return make_uint2(s0, s1);
}
__device__ __forceinline__ float4 h2x2_to_f4(uint2 u) {
    float2 a = __half22float2(*reinterpret_cast<__half2*>(&u.x));
    float2 b = __half22float2(*reinterpret_cast<__half2*>(&u.y));
    return make_float4(a.x, a.y, b.x, b.y);
}

__device__ __forceinline__ void mma_bf16(float* c, const uint32_t* a, const uint32_t* b) {
    asm volatile(
        "mma.sync.aligned.m16n8k16.row.col.f32.bf16.bf16.f32 "
        "{%0,%1,%2,%3}, {%4,%5,%6,%7}, {%8,%9}, {%0,%1,%2,%3};\n"
        : "+f"(c[0]), "+f"(c[1]), "+f"(c[2]), "+f"(c[3])
        : "r"(a[0]), "r"(a[1]), "r"(a[2]), "r"(a[3]), "r"(b[0]), "r"(b[1]));
}
__device__ __forceinline__ void mma_f16(float* c, const uint32_t* a, const uint32_t* b) {
    asm volatile(
        "mma.sync.aligned.m16n8k16.row.col.f32.f16.f16.f32 "
        "{%0,%1,%2,%3}, {%4,%5,%6,%7}, {%8,%9}, {%0,%1,%2,%3};\n"
        : "+f"(c[0]), "+f"(c[1]), "+f"(c[2]), "+f"(c[3])
        : "r"(a[0]), "r"(a[1]), "r"(a[2]), "r"(a[3]), "r"(b[0]), "r"(b[1]));
}

// ---------------- CSR build ----------------
__global__ void count_deg(const int2* __restrict__ dst2, int* __restrict__ cnt, int e2) {
    int i = blockIdx.x * blockDim.x + threadIdx.x;
    if (i < e2) {
        int2 d = dst2[i];
        atomicAdd(&cnt[d.x], 1);
        atomicAdd(&cnt[d.y], 1);
    }
}

__global__ void scan1(const int* __restrict__ cnt, int* __restrict__ off,
                      float* __restrict__ dinv, int* __restrict__ bsum) {
    __shared__ int sm[1024];
    int tid = threadIdx.x;
    int i = blockIdx.x * 1024 + tid;
    int c = (i < N_NODES) ? cnt[i] : 0;
    if (i < N_NODES) dinv[i] = rsqrtf((float)c + 1.0f);
    sm[tid] = c;
    __syncthreads();
    for (int d = 1; d < 1024; d <<= 1) {
        int t = (tid >= d) ? sm[tid - d] : 0;
        __syncthreads();
        sm[tid] += t;
        __syncthreads();
    }
    if (i < N_NODES) off[i] = sm[tid] - c;
    if (tid == 1023) bsum[blockIdx.x] = sm[1023];
}

__global__ void scan_add(int* __restrict__ off, const int* __restrict__ bsum) {
    __shared__ int pre[32];
    int tid = threadIdx.x;
    if (tid < 32) {
        int v = (tid < SCAN_BLOCKS) ? bsum[tid] : 0;
#pragma unroll
        for (int d = 1; d < 32; d <<= 1) {
            int t = __shfl_up_sync(0xffffffffu, v, d);
            if (tid >= d) v += t;
        }
        pre[tid] = v;
    }
    __syncthreads();
    int b = blockIdx.x;
    int add = (b == 0) ? 0 : pre[b - 1];
    int i = b * 1024 + tid;
    if (i < N_NODES && b > 0) off[i] += add;
    if (b == 0 && tid == 0) off[N_NODES] = N_EDGES;
}

// scatter edges (consumes cnt) + y0 = fp16(dinv * x), row stride 40 uint (80 feats)
__global__ void scatter_scale(const int* __restrict__ src, const int* __restrict__ dst,
                              const int* __restrict__ off, int* __restrict__ cnt,
                              int* __restrict__ csr, const float* __restrict__ dinv,
                              const float2* __restrict__ x2, uint32_t* __restrict__ yh) {
    int t = blockIdx.x * blockDim.x + threadIdx.x;
    if (t < N_EDGES) {
        int d = dst[t];
        int pos = off[d] + atomicSub(&cnt[d], 1) - 1;
        csr[pos] = src[t];
    }
    const int DP = D1 / 2;  // 39 pairs
    int total = N_NODES * DP;
    int stride = gridDim.x * blockDim.x;
    for (int i = t; i < total; i += stride) {
        int node = i / DP;
        int f = i - node * DP;
        float2 v = x2[i];
        float di = dinv[node];
        yh[node * 40 + f] = pack_h2(di * v.x, di * v.y);
    }
}

// ---------------- fused: zero cnt + weight -> fragment conversion ----------------
__global__ void conv_all(const float* __restrict__ W1, const float* __restrict__ W2,
                         const float* __restrict__ W3, const float* __restrict__ Wf1,
                         const float* __restrict__ Wf2, uint4* __restrict__ out,
                         int4* __restrict__ cnt4) {
    int zi = blockIdx.x * 256 + threadIdx.x;
    if (zi < N_NODES / 4) cnt4[zi] = make_int4(0, 0, 0, 0);

    int unit = blockIdx.x * 8 + (threadIdx.x >> 5);
    int lane = threadIdx.x & 31;
    const float* W; int K, N, NG, base, u;
    bool h16;
    if (unit < 50)        { W = W1;  K = 78;   N = 78;   NG = 10;  base = WF_OFF1;  u = unit;        h16 = true; }
    else if (unit < 150)  { W = W2;  K = 78;   N = 156;  NG = 20;  base = WF_OFF2;  u = unit - 50;   h16 = true; }
    else if (unit < 540)  { W = W3;  K = 156;  N = 312;  NG = 39;  base = WF_OFF3;  u = unit - 150;  h16 = true; }
    else if (unit < 3100) { W = Wf1; K = 312;  N = 1024; NG = 128; base = WF_OFFF1; u = unit - 540;  h16 = false; }
    else if (unit < 4124) { W = Wf2; K = 1024; N = 128;  NG = 16;  base = WF_OFFF2; u = unit - 3100; h16 = false; }
    else return;
    int chunk = u / NG, ng = u % NG;
    int n = ng * 8 + (lane >> 2);
    int k0 = chunk * 16 + 2 * (lane & 3);
    float f[4];
#pragma unroll
    for (int j = 0; j < 4; j++) {
        int k = k0 + (j >> 1) * 8 + (j & 1);
        f[j] = (k < K && n < N) ? W[(size_t)k * N + n] : 0.f;
    }
    uint2 p0 = h16 ? split2h(f[0], f[1]) : split2(f[0], f[1]);
    uint2 p1 = h16 ? split2h(f[2], f[3]) : split2(f[2], f[3]);
    out[base + (size_t)u * 32 + lane] = make_uint4(p0.x, p1.x, p0.y, p1.y);
}

// ---------------- aggregation over fp16 y, fp32 accumulate, fp16 out ----------
// a = dinv[i]*(y[i]+sum_e y[src]); y pre-scaled by dinv. uint2 = 4 features.
template <int Q, int QS, int P>
__global__ void aggregate_h2(const uint2* __restrict__ y2, const int* __restrict__ off,
                             const int* __restrict__ csr, const float* __restrict__ dinv,
                             uint32_t* __restrict__ outA) {
    int node = blockIdx.x * blockDim.y + threadIdx.y;
    if (node >= N_NODES) return;
    int f = threadIdx.x;
    int beg = off[node], end = off[node + 1];
    const uint2* yb = y2 + f;
    float4 acc = h2x2_to_f4(yb[(size_t)node * QS]);
    int e = beg;
    for (; e + 4 <= end; e += 4) {
        int s0 = csr[e], s1 = csr[e + 1], s2 = csr[e + 2], s3 = csr[e + 3];
        float4 v0 = h2x2_to_f4(yb[(size_t)s0 * QS]);
        float4 v1 = h2x2_to_f4(yb[(size_t)s1 * QS]);
        float4 v2 = h2x2_to_f4(yb[(size_t)s2 * QS]);
        float4 v3 = h2x2_to_f4(yb[(size_t)s3 * QS]);
        acc.x += (v0.x + v1.x) + (v2.x + v3.x);
        acc.y += (v0.y + v1.y) + (v2.y + v3.y);
        acc.z += (v0.z + v1.z) + (v2.z + v3.z);
        acc.w += (v0.w + v1.w) + (v2.w + v3.w);
    }
    for (; e < end; e++) {
        int s = csr[e];
        float4 v = h2x2_to_f4(yb[(size_t)s * QS]);
        acc.x += v.x; acc.y += v.y; acc.z += v.z; acc.w += v.w;
    }
    float di = dinv[node];
    if (2 * f < P)
        outA[(size_t)node * P + 2 * f] = pack_h2(di * acc.x, di * acc.y);
    if (2 * f + 1 < P)
        outA[(size_t)node * P + 2 * f + 1] = pack_h2(di * acc.z, di * acc.w);
}

// ---------------- node GEMM: fp16 A (1 plane) x split-fp16 W (2 mma/step) ----------
// out: fp16 half2 rows, stride strideC uints. relu always; optional rowscale.
template <int MI, bool SCALE>
__global__ __launch_bounds__(256) void gemm_f16a(const uint32_t* __restrict__ A, int KP,
                                                 const uint4* __restrict__ BF, int NG,
                                                 const float* __restrict__ bias,
                                                 const float* __restrict__ rowscale,
                                                 uint32_t* __restrict__ Ch,
                                                 int M, int N, int strideC) {
    constexpr int GI = 2 * MI;
    constexpr int PLANE = GI * 128;
    __shared__ uint32_t ASw[PLANE];
    const uint4* ASf4 = reinterpret_cast<const uint4*>(ASw);
    int tid = threadIdx.x;
    int warp = tid >> 5, lane = tid & 31;
    int g = lane >> 2, tig = lane & 3;
    int wm = warp >> 2, wn = warp & 3;
    int row0 = blockIdx.y * (16 * GI), col0 = blockIdx.x * 64;
    int chunks = (2 * KP + 15) >> 4;

    int li[MI], gbase[MI], colc[MI];
    bool rowok[MI];
#pragma unroll
    for (int j = 0; j < MI; j++) {
        int i = tid + j * 256;
        int m = i >> 3, c = i & 7;
        int gi = m >> 4;
        int fl = ((m & 7) << 2) | (c & 3);
        int reg = ((m >> 3) & 1) | ((c >> 2) << 1);
        li[j] = ((gi * 32 + fl) << 2) + reg;
        rowok[j] = (row0 + m) < M;
        gbase[j] = (row0 + m) * KP + c;
        colc[j] = c;
    }
    int ngBase = (col0 >> 3) + wn * 2;
    bool ngok0 = (ngBase < NG), ngok1 = (ngBase + 1 < NG);
    const uint4* BF0 = BF + (size_t)ngBase * 32 + lane;
    const uint4* BF1 = BF + (size_t)(ngBase + 1) * 32 + lane;

    float acc[MI][2][4];
#pragma unroll
    for (int a = 0; a < MI; a++)
#pragma unroll
        for (int b = 0; b < 2; b++)
#pragma unroll
            for (int c = 0; c < 4; c++) acc[a][b][c] = 0.f;

    for (int ch = 0; ch < chunks; ch++) {
        uint4 bfr[2];
        size_t bo = (size_t)ch * NG * 32;
        bfr[0] = ngok0 ? BF0[bo] : make_uint4(0, 0, 0, 0);
        bfr[1] = ngok1 ? BF1[bo] : make_uint4(0, 0, 0, 0);
        int gc = 8 * ch;
#pragma unroll
        for (int j = 0; j < MI; j++) {
            uint32_t v = (rowok[j] && colc[j] + gc < KP) ? A[gbase[j] + gc] : 0u;
            ASw[li[j]] = v;
        }
        __syncthreads();

#pragma unroll
        for (int mi = 0; mi < MI; mi++) {
            int gi = wm * MI + mi;
            uint4 av = ASf4[gi * 32 + lane];
            const uint32_t* a = reinterpret_cast<const uint32_t*>(&av);
#pragma unroll
            for (int ni = 0; ni < 2; ni++) {
                uint32_t b0[2] = {bfr[ni].x, bfr[ni].y};
                uint32_t b1[2] = {bfr[ni].z, bfr[ni].w};
                mma_f16(acc[mi][ni], a, b0);   // A * Whi
                mma_f16(acc[mi][ni], a, b1);   // A * Wlo
            }
        }
        __syncthreads();
    }

#pragma unroll
    for (int mi = 0; mi < MI; mi++) {
        int r0 = row0 + wm * (MI * 16) + mi * 16 + g;
        int r1 = r0 + 8;
        float sc0 = 1.f, sc1 = 1.f;
        if (SCALE) {
            if (r0 < M) sc0 = rowscale[r0];
            if (r1 < M) sc1 = rowscale[r1];
        }
#pragma unroll
        for (int ni = 0; ni < 2; ni++) {
            int c0 = col0 + wn * 16 + ni * 8 + tig * 2;
            if (c0 < N) {
                float2 bia = *reinterpret_cast<const float2*>(&bias[c0]);
                if (r0 < M) {
                    float vx = fmaxf(acc[mi][ni][0] + bia.x, 0.f) * sc0;
                    float vy = fmaxf(acc[mi][ni][1] + bia.y, 0.f) * sc0;
                    Ch[(size_t)r0 * strideC + (c0 >> 1)] = pack_h2(vx, vy);
                }
                if (r1 < M) {
                    float vx = fmaxf(acc[mi][ni][2] + bia.x, 0.f) * sc1;
                    float vy = fmaxf(acc[mi][ni][3] + bia.y, 0.f) * sc1;
                    Ch[(size_t)r1 * strideC + (c0 >> 1)] = pack_h2(vx, vy);
                }
            }
        }
    }
}

// ---------------- FC GEMM: split-bf16 A + W (R10 proven) ----------------
// OMODE: 0 = f32 float2, 1 = split-bf16 uint2
template <int MI, bool RELU, int OMODE>
__global__ __launch_bounds__(256) void gemm_bf16s(const uint2* __restrict__ A, int KP,
                                                  const uint4* __restrict__ BF, int NG,
                                                  const float* __restrict__ bias,
                                                  float* __restrict__ Cf,
                                                  uint2* __restrict__ Cs,
                                                  int M, int N, int K, int strideC) {
    constexpr int GI = 2 * MI;
    constexpr int BM = 16 * GI;
    constexpr int PLANE = GI * 128;
    __shared__ uint32_t ASw[2 * PLANE];
    const uint4* ASf4 = reinterpret_cast<const uint4*>(ASw);
    int tid = threadIdx.x;
    int warp = tid >> 5, lane = tid & 31;
    int g = lane >> 2, tig = lane & 3;
    int wm = warp >> 2, wn = warp & 3;
    int row0 = blockIdx.y * BM, col0 = blockIdx.x * 64;
    int chunks = (K + 15) >> 4;

    int li[MI], gbase[MI], colc[MI];
    bool rowok[MI];
#pragma unroll
    for (int j = 0; j < MI; j++) {
        int i = tid + j * 256;
        int m = i >> 3, c = i & 7;
        int gi = m >> 4;
        int fl = ((m & 7) << 2) | (c & 3);
        int reg = ((m >> 3) & 1) | ((c >> 2) << 1);
        li[j] = ((gi * 32 + fl) << 2) + reg;
        rowok[j] = (row0 + m) < M;
        gbase[j] = (row0 + m) * KP + c;
        colc[j] = c;
    }
    int ngBase = (col0 >> 3) + wn * 2;
    bool ngok0 = (ngBase < NG), ngok1 = (ngBase + 1 < NG);
    const uint4* BF0 = BF + (size_t)ngBase * 32 + lane;
    const uint4* BF1 = BF + (size_t)(ngBase + 1) * 32 + lane;

    float acc[MI][2][4];
#pragma unroll
    for (int a = 0; a < MI; a++)
#pragma unroll
        for (int b = 0; b < 2; b++)
#pragma unroll
            for (int c = 0; c < 4; c++) acc[a][b][c] = 0.f;

    for (int ch = 0; ch < chunks; ch++) {
        uint4 bfr[2];
        size_t bo = (size_t)ch * NG * 32;
        bfr[0] = ngok0 ? BF0[bo] : make_uint4(0, 0, 0, 0);
        bfr[1] = ngok1 ? BF1[bo] : make_uint4(0, 0, 0, 0);
        int gc = 8 * ch;
#pragma unroll
        for (int j = 0; j < MI; j++) {
            uint2 v = (rowok[j] && colc[j] + gc < KP) ? A[gbase[j] + gc] : make_uint2(0, 0);
            ASw[li[j]] = v.x;
            ASw[li[j] + PLANE] = v.y;
        }
        __syncthreads();
#pragma unroll
        for (int mi = 0; mi < MI; mi++) {
            int gi = wm * MI + mi;
            uint4 a0v = ASf4[gi * 32 + lane];
            uint4 a1v = ASf4[PLANE / 4 + gi * 32 + lane];
            const uint32_t* a0 = reinterpret_cast<const uint32_t*>(&a0v);
            const uint32_t* a1 = reinterpret_cast<const uint32_t*>(&a1v);
#pragma unroll
            for (int ni = 0; ni < 2; ni++) {
                uint32_t b0[2] = {bfr[ni].x, bfr[ni].y};
                uint32_t b1[2] = {bfr[ni].z, bfr[ni].w};
                mma_bf16(acc[mi][ni], a0, b0);
                mma_bf16(acc[mi][ni], a1, b0);
                mma_bf16(acc[mi][ni], a0, b1);
            }
        }
        __syncthreads();
    }

#pragma unroll
    for (int mi = 0; mi < MI; mi++) {
        int r0 = row0 + wm * (MI * 16) + mi * 16 + g;
        int r1 = r0 + 8;
#pragma unroll
        for (int ni = 0; ni < 2; ni++) {
            int c0 = col0 + wn * 16 + ni * 8 + tig * 2;
            if (c0 < N) {
                float2 bia = *reinterpret_cast<const float2*>(&bias[c0]);
                if (r0 < M) {
                    float vx = acc[mi][ni][0] + bia.x, vy = acc[mi][ni][1] + bia.y;
                    if (RELU) { vx = fmaxf(vx, 0.f); vy = fmaxf(vy, 0.f); }
                    if (OMODE == 1) Cs[(size_t)r0 * (N >> 1) + (c0 >> 1)] = split2(vx, vy);
                    else *reinterpret_cast<float2*>(&Cf[(size_t)r0 * strideC + c0]) = make_float2(vx, vy);
                }
                if (r1 < M) {
                    float vx = acc[mi][ni][2] + bia.x, vy = acc[mi][ni][3] + bia.y;
                    if (RELU) { vx = fmaxf(vx, 0.f); vy = fmaxf(vy, 0.f); }
                    if (OMODE == 1) Cs[(size_t)r1 * (N >> 1) + (c0 >> 1)] = split2(vx, vy);
                    else *reinterpret_cast<float2*>(&Cf[(size_t)r1 * strideC + c0]) = make_float2(vx, vy);
                }
            }
        }
    }
}

// ---------------- max pool over fp16 h3 (row stride 80 uint2 = 320 feats) -----------
__global__ void pool_kernel(const uint2* __restrict__ h2v, const int* __restrict__ batch,
                            uint2* __restrict__ pooledS) {
    __shared__ int sb[2];
    __shared__ float4 red[4][80];
    int lane = threadIdx.x, ty = threadIdx.y, gr = blockIdx.x;
    if (ty == 0 && lane < 2) {
        int target = gr + lane, lo = 0, hi = N_NODES;
        while (lo < hi) { int mid = (lo + hi) >> 1; if (batch[mid] < target) lo = mid + 1; else hi = mid; }
        sb[lane] = lo;
    }
    __syncthreads();
    int beg = sb[0], end = sb[1];
    const int DQ = D3 / 4;
    float4 m = make_float4(0.f, 0.f, 0.f, 0.f);
    if (lane < DQ) {
        for (int node = beg + ty; node < end; node += 4) {
            float4 v = h2x2_to_f4(h2v[(size_t)node * 80 + lane]);
            m.x = fmaxf(m.x, v.x); m.y = fmaxf(m.y, v.y);
            m.z = fmaxf(m.z, v.z); m.w = fmaxf(m.w, v.w);
        }
    }
    red[ty][lane] = m;
    __syncthreads();
    if (ty == 0 && lane < DQ) {
        float4 a = red[0][lane], b = red[1][lane], c = red[2][lane], d = red[3][lane];
        float4 r;
        r.x = fmaxf(fmaxf(a.x, b.x), fmaxf(c.x, d.x));
        r.y = fmaxf(fmaxf(a.y, b.y), fmaxf(c.y, d.y));
        r.z = fmaxf(fmaxf(a.z, b.z), fmaxf(c.z, d.z));
        r.w = fmaxf(fmaxf(a.w, b.w), fmaxf(c.w, d.w));
        pooledS[(size_t)gr * (D3 / 2) + 2 * lane]     = split2(r.x, r.y);
        pooledS[(size_t)gr * (D3 / 2) + 2 * lane + 1] = split2(r.z, r.w);
    }
}

// ---------------- launch ----------------
extern "C" void kernel_launch(void* const* d_in, const int* in_sizes, int n_in,
                              void* d_out, int out_size) {
    const float* x     = (const float*)d_in[0];
    const int*   ei    = (const int*)d_in[1];
    const int*   batch = (const int*)d_in[2];
    const float* W1 = (const float*)d_in[3];  const float* b1  = (const float*)d_in[4];
    const float* W2 = (const float*)d_in[5];  const float* b2  = (const float*)d_in[6];
    const float* W3 = (const float*)d_in[7];  const float* b3  = (const float*)d_in[8];
    const float* Wf1 = (const float*)d_in[9]; const float* bf1 = (const float*)d_in[10];
    const float* Wf2 = (const float*)d_in[11];const float* bf2 = (const float*)d_in[12];
    float* out = (float*)d_out;

    const int* src = ei;
    const int* dst = ei + N_EDGES;

    int *cnt, *off, *csr, *bsum;
    float *dinv;
    uint2 *yh, *pooledS, *fc1S;
    uint32_t *sA;
    uint4 *wf;
    cudaGetSymbolAddress((void**)&cnt, g_cnt);
    cudaGetSymbolAddress((void**)&off, g_off);
    cudaGetSymbolAddress((void**)&csr, g_csr);
    cudaGetSymbolAddress((void**)&bsum, g_bsum);
    cudaGetSymbolAddress((void**)&dinv, g_dinv);
    cudaGetSymbolAddress((void**)&yh, g_yh);
    cudaGetSymbolAddress((void**)&sA, g_sA);
    cudaGetSymbolAddress((void**)&pooledS, g_pooledS);
    cudaGetSymbolAddress((void**)&fc1S, g_fc1S);
    cudaGetSymbolAddress((void**)&wf, g_wfrag);
    uint32_t* yhu = (uint32_t*)yh;

    // ---- fused zero(cnt) + weight fragment conversion ----
    conv_all<<<(4124 + 7) / 8, 256>>>(W1, W2, W3, Wf1, Wf2, wf, (int4*)cnt);

    // ---- CSR build + y0 = fp16(dinv*x), stride 40 uint ----
    count_deg<<<(N_EDGES / 2 + 255) / 256, 256>>>((const int2*)dst, cnt, N_EDGES / 2);
    scan1<<<SCAN_BLOCKS, 1024>>>(cnt, off, dinv, bsum);
    scan_add<<<SCAN_BLOCKS, 1024>>>(off, bsum);
    scatter_scale<<<(N_EDGES + 255) / 256, 256>>>(src, dst, off, cnt, csr, dinv,
                                                  (const float2*)x, yhu);

    const int RB256 = (N_NODES + 255) / 256;  // 118

    // ---- layer 1: y1 = fp16(dinv*relu(agg(y0)@W1+b1)), stride 40 uint ----
    aggregate_h2<20, 20, 39><<<(N_NODES + 11) / 12, dim3(20, 12)>>>(yh, off, csr, dinv, sA);
    gemm_f16a<8, true><<<dim3(2, RB256), 256>>>(
        sA, 39, wf + WF_OFF1, 10, b1, dinv, yhu, N_NODES, D1, 40);

    // ---- layer 2: y2 stride 80 uint ----
    aggregate_h2<20, 20, 39><<<(N_NODES + 11) / 12, dim3(20, 12)>>>(yh, off, csr, dinv, sA);
    gemm_f16a<8, true><<<dim3(3, RB256), 256>>>(
        sA, 39, wf + WF_OFF2, 20, b2, dinv, yhu, N_NODES, D2, 80);

    // ---- layer 3: h3 stride 160 uint (unscaled, feeds pooling) ----
    aggregate_h2<40, 40, 78><<<(N_NODES + 5) / 6, dim3(40, 6)>>>(yh, off, csr, dinv, sA);
    gemm_f16a<8, false><<<dim3(5, RB256), 256>>>(
        sA, 78, wf + WF_OFF3, 39, b3, nullptr, yhu, N_NODES, D3, 160);

    // ---- pool ----
    pool_kernel<<<N_GRAPHS, dim3(80, 4)>>>(yh, batch, pooledS);

    // ---- FC head (split-bf16 fp32-accurate path, unchanged) ----
    gemm_bf16s<4, true, 1><<<dim3(16, (N_GRAPHS + 127) / 128), 256>>>(
        pooledS, D3 / 2, wf + WF_OFFF1, 128, bf1, nullptr, fc1S, N_GRAPHS, 1024, D3, 0);
    gemm_bf16s<4, false, 0><<<dim3(2, (N_GRAPHS + 127) / 128), 256>>>(
        fc1S, 512, wf + WF_OFFF2, 16, bf2, out, nullptr, N_GRAPHS, 128, 1024, 128);
}

// round 16
// speedup vs baseline: 1.4718x; 1.0315x over previous
#include <cuda_runtime.h>
#include <cuda_bf16.h>
#include <cuda_fp16.h>
#include <cstdint>

#define N_NODES  30000
#define N_EDGES  480000
#define N_GRAPHS 500
#define D1 78
#define D2 156
#define D3 312
#define SCAN_BLOCKS 30   // ceil(30000/1024)

// ---------------- scratch ----------------
__device__ int   g_cnt[N_NODES];
__device__ int   g_off[N_NODES + 1];
__device__ int   g_bsum[SCAN_BLOCKS];
__device__ int   g_csr[N_EDGES];
__device__ float g_dinv[N_NODES];
__device__ uint2 g_yh[(size_t)N_NODES * 80];         // fp16 activations (half2-packed, padded)
__device__ uint32_t g_sA[(size_t)N_NODES * D1];      // fp16 GEMM A (pairs; max 78/row)
__device__ uint2 g_pooledS[N_GRAPHS * (D3 / 2)];
__device__ uint2 g_fc1S[N_GRAPHS * 512];
// node-layer weight fragments: plain fp16, uint2 per (chunk,ng,lane)
#define WH_OFF1 0
#define WH_OFF2 1600      // 5*10*32
#define WH_OFF3 4800      // +5*20*32
#define WH_TOTAL 17280    // +10*39*32
__device__ uint2 g_wfragh[WH_TOTAL];
// FC weight fragments: split-bf16, uint4 per (chunk,ng,lane)
#define WF_OFFF1 0
#define WF_OFFF2 81920    // 20*128*32
#define WF_TOTAL 114688   // +64*16*32
__device__ uint4 g_wfrag[WF_TOTAL];

// ---------------- helpers ----------------
__device__ __forceinline__ uint32_t pack_bf16x2(float lo, float hi) {
    uint32_t r;
    asm("cvt.rn.bf16x2.f32 %0, %1, %2;" : "=r"(r) : "f"(hi), "f"(lo));
    return r;
}
__device__ __forceinline__ uint2 split2(float x, float y) {      // split-bf16 (FC path)
    uint32_t s0 = pack_bf16x2(x, y);
    float r0 = x - __uint_as_float(s0 << 16);
    float r1 = y - __uint_as_float(s0 & 0xffff0000u);
    uint32_t s1 = pack_bf16x2(r0, r1);
    return make_uint2(s0, s1);
}
__device__ __forceinline__ uint32_t pack_h2(float a, float b) {
    __half2 h = __floats2half2_rn(a, b);
    return *reinterpret_cast<uint32_t*>(&h);
}
__device__ __forceinline__ float4 h2x2_to_f4(uint2 u) {
    float2 a = __half22float2(*reinterpret_cast<__half2*>(&u.x));
    float2 b = __half22float2(*reinterpret_cast<__half2*>(&u.y));
    return make_float4(a.x, a.y, b.x, b.y);
}

__device__ __forceinline__ void mma_bf16(float* c, const uint32_t* a, const uint32_t* b) {
    asm volatile(
        "mma.sync.aligned.m16n8k16.row.col.f32.bf16.bf16.f32 "
        "{%0,%1,%2,%3}, {%4,%5,%6,%7}, {%8,%9}, {%0,%1,%2,%3};\n"
        : "+f"(c[0]), "+f"(c[1]), "+f"(c[2]), "+f"(c[3])
        : "r"(a[0]), "r"(a[1]), "r"(a[2]), "r"(a[3]), "r"(b[0]), "r"(b[1]));
}
__device__ __forceinline__ void mma_f16(float* c, const uint32_t* a, const uint32_t* b) {
    asm volatile(
        "mma.sync.aligned.m16n8k16.row.col.f32.f16.f16.f32 "
        "{%0,%1,%2,%3}, {%4,%5,%6,%7}, {%8,%9}, {%0,%1,%2,%3};\n"
        : "+f"(c[0]), "+f"(c[1]), "+f"(c[2]), "+f"(c[3])
        : "r"(a[0]), "r"(a[1]), "r"(a[2]), "r"(a[3]), "r"(b[0]), "r"(b[1]));
}

// ---------------- CSR build ----------------
__global__ void count_deg(const int2* __restrict__ dst2, int* __restrict__ cnt, int e2) {
    int i = blockIdx.x * blockDim.x + threadIdx.x;
    if (i < e2) {
        int2 d = dst2[i];
        atomicAdd(&cnt[d.x], 1);
        atomicAdd(&cnt[d.y], 1);
    }
}

__global__ void scan1(const int* __restrict__ cnt, int* __restrict__ off,
                      float* __restrict__ dinv, int* __restrict__ bsum) {
    __shared__ int sm[1024];
    int tid = threadIdx.x;
    int i = blockIdx.x * 1024 + tid;
    int c = (i < N_NODES) ? cnt[i] : 0;
    if (i < N_NODES) dinv[i] = rsqrtf((float)c + 1.0f);
    sm[tid] = c;
    __syncthreads();
    for (int d = 1; d < 1024; d <<= 1) {
        int t = (tid >= d) ? sm[tid - d] : 0;
        __syncthreads();
        sm[tid] += t;
        __syncthreads();
    }
    if (i < N_NODES) off[i] = sm[tid] - c;
    if (tid == 1023) bsum[blockIdx.x] = sm[1023];
}

__global__ void scan_add(int* __restrict__ off, const int* __restrict__ bsum) {
    __shared__ int pre[32];
    int tid = threadIdx.x;
    if (tid < 32) {
        int v = (tid < SCAN_BLOCKS) ? bsum[tid] : 0;
#pragma unroll
        for (int d = 1; d < 32; d <<= 1) {
            int t = __shfl_up_sync(0xffffffffu, v, d);
            if (tid >= d) v += t;
        }
        pre[tid] = v;
    }
    __syncthreads();
    int b = blockIdx.x;
    int add = (b == 0) ? 0 : pre[b - 1];
    int i = b * 1024 + tid;
    if (i < N_NODES && b > 0) off[i] += add;
    if (b == 0 && tid == 0) off[N_NODES] = N_EDGES;
}

// scatter edges (consumes cnt) + y0 = fp16(dinv * x), row stride 40 uint (80 feats)
__global__ void scatter_scale(const int* __restrict__ src, const int* __restrict__ dst,
                              const int* __restrict__ off, int* __restrict__ cnt,
                              int* __restrict__ csr, const float* __restrict__ dinv,
                              const float2* __restrict__ x2, uint32_t* __restrict__ yh) {
    int t = blockIdx.x * blockDim.x + threadIdx.x;
    if (t < N_EDGES) {
        int d = dst[t];
        int pos = off[d] + atomicSub(&cnt[d], 1) - 1;
        csr[pos] = src[t];
    }
    const int DP = D1 / 2;  // 39 pairs
    int total = N_NODES * DP;
    int stride = gridDim.x * blockDim.x;
    for (int i = t; i < total; i += stride) {
        int node = i / DP;
        int f = i - node * DP;
        float2 v = x2[i];
        float di = dinv[node];
        yh[node * 40 + f] = pack_h2(di * v.x, di * v.y);
    }
}

// ---------------- fused: zero cnt + weight -> fragment conversion ----------------
__global__ void conv_all(const float* __restrict__ W1, const float* __restrict__ W2,
                         const float* __restrict__ W3, const float* __restrict__ Wf1,
                         const float* __restrict__ Wf2,
                         uint2* __restrict__ outh, uint4* __restrict__ out,
                         int4* __restrict__ cnt4) {
    int zi = blockIdx.x * 256 + threadIdx.x;
    if (zi < N_NODES / 4) cnt4[zi] = make_int4(0, 0, 0, 0);

    int unit = blockIdx.x * 8 + (threadIdx.x >> 5);
    int lane = threadIdx.x & 31;
    const float* W; int K, N, NG, base, u;
    bool h16;
    if (unit < 50)        { W = W1;  K = 78;   N = 78;   NG = 10;  base = WH_OFF1;  u = unit;        h16 = true; }
    else if (unit < 150)  { W = W2;  K = 78;   N = 156;  NG = 20;  base = WH_OFF2;  u = unit - 50;   h16 = true; }
    else if (unit < 540)  { W = W3;  K = 156;  N = 312;  NG = 39;  base = WH_OFF3;  u = unit - 150;  h16 = true; }
    else if (unit < 3100) { W = Wf1; K = 312;  N = 1024; NG = 128; base = WF_OFFF1; u = unit - 540;  h16 = false; }
    else if (unit < 4124) { W = Wf2; K = 1024; N = 128;  NG = 16;  base = WF_OFFF2; u = unit - 3100; h16 = false; }
    else return;
    int chunk = u / NG, ng = u % NG;
    int n = ng * 8 + (lane >> 2);
    int k0 = chunk * 16 + 2 * (lane & 3);
    float f[4];
#pragma unroll
    for (int j = 0; j < 4; j++) {
        int k = k0 + (j >> 1) * 8 + (j & 1);
        f[j] = (k < K && n < N) ? W[(size_t)k * N + n] : 0.f;
    }
    if (h16) {
        outh[base + (size_t)u * 32 + lane] = make_uint2(pack_h2(f[0], f[1]), pack_h2(f[2], f[3]));
    } else {
        uint2 p0 = split2(f[0], f[1]);
        uint2 p1 = split2(f[2], f[3]);
        out[base + (size_t)u * 32 + lane] = make_uint4(p0.x, p1.x, p0.y, p1.y);
    }
}

// ---------------- aggregation over fp16 y, fp32 accumulate, fp16 out ----------
template <int Q, int QS, int P>
__global__ void aggregate_h2(const uint2* __restrict__ y2, const int* __restrict__ off,
                             const int* __restrict__ csr, const float* __restrict__ dinv,
                             uint32_t* __restrict__ outA) {
    int node = blockIdx.x * blockDim.y + threadIdx.y;
    if (node >= N_NODES) return;
    int f = threadIdx.x;
    int beg = off[node], end = off[node + 1];
    const uint2* yb = y2 + f;
    float4 acc = h2x2_to_f4(yb[(size_t)node * QS]);
    int e = beg;
    for (; e + 4 <= end; e += 4) {
        int s0 = csr[e], s1 = csr[e + 1], s2 = csr[e + 2], s3 = csr[e + 3];
        float4 v0 = h2x2_to_f4(yb[(size_t)s0 * QS]);
        float4 v1 = h2x2_to_f4(yb[(size_t)s1 * QS]);
        float4 v2 = h2x2_to_f4(yb[(size_t)s2 * QS]);
        float4 v3 = h2x2_to_f4(yb[(size_t)s3 * QS]);
        acc.x += (v0.x + v1.x) + (v2.x + v3.x);
        acc.y += (v0.y + v1.y) + (v2.y + v3.y);
        acc.z += (v0.z + v1.z) + (v2.z + v3.z);
        acc.w += (v0.w + v1.w) + (v2.w + v3.w);
    }
    for (; e < end; e++) {
        int s = csr[e];
        float4 v = h2x2_to_f4(yb[(size_t)s * QS]);
        acc.x += v.x; acc.y += v.y; acc.z += v.z; acc.w += v.w;
    }
    float di = dinv[node];
    if (2 * f < P)
        outA[(size_t)node * P + 2 * f] = pack_h2(di * acc.x, di * acc.y);
    if (2 * f + 1 < P)
        outA[(size_t)node * P + 2 * f + 1] = pack_h2(di * acc.z, di * acc.w);
}

// ---------------- node GEMM: fp16 A x fp16 W, 1 mma/step ----------
template <int MI, bool SCALE>
__global__ __launch_bounds__(256) void gemm_f16a(const uint32_t* __restrict__ A, int KP,
                                                 const uint2* __restrict__ BF, int NG,
                                                 const float* __restrict__ bias,
                                                 const float* __restrict__ rowscale,
                                                 uint32_t* __restrict__ Ch,
                                                 int M, int N, int strideC) {
    constexpr int GI = 2 * MI;
    constexpr int PLANE = GI * 128;
    __shared__ uint32_t ASw[PLANE];
    const uint4* ASf4 = reinterpret_cast<const uint4*>(ASw);
    int tid = threadIdx.x;
    int warp = tid >> 5, lane = tid & 31;
    int g = lane >> 2, tig = lane & 3;
    int wm = warp >> 2, wn = warp & 3;
    int row0 = blockIdx.y * (16 * GI), col0 = blockIdx.x * 64;
    int chunks = (2 * KP + 15) >> 4;

    int li[MI], gbase[MI], colc[MI];
    bool rowok[MI];
#pragma unroll
    for (int j = 0; j < MI; j++) {
        int i = tid + j * 256;
        int m = i >> 3, c = i & 7;
        int gi = m >> 4;
        int fl = ((m & 7) << 2) | (c & 3);
        int reg = ((m >> 3) & 1) | ((c >> 2) << 1);
        li[j] = ((gi * 32 + fl) << 2) + reg;
        rowok[j] = (row0 + m) < M;
        gbase[j] = (row0 + m) * KP + c;
        colc[j] = c;
    }
    int ngBase = (col0 >> 3) + wn * 2;
    bool ngok0 = (ngBase < NG), ngok1 = (ngBase + 1 < NG);
    const uint2* BF0 = BF + (size_t)ngBase * 32 + lane;
    const uint2* BF1 = BF + (size_t)(ngBase + 1) * 32 + lane;

    float acc[MI][2][4];
#pragma unroll
    for (int a = 0; a < MI; a++)
#pragma unroll
        for (int b = 0; b < 2; b++)
#pragma unroll
            for (int c = 0; c < 4; c++) acc[a][b][c] = 0.f;

    for (int ch = 0; ch < chunks; ch++) {
        uint2 bfr[2];
        size_t bo = (size_t)ch * NG * 32;
        bfr[0] = ngok0 ? BF0[bo] : make_uint2(0, 0);
        bfr[1] = ngok1 ? BF1[bo] : make_uint2(0, 0);
        int gc = 8 * ch;
#pragma unroll
        for (int j = 0; j < MI; j++) {
            uint32_t v = (rowok[j] && colc[j] + gc < KP) ? A[gbase[j] + gc] : 0u;
            ASw[li[j]] = v;
        }
        __syncthreads();

#pragma unroll
        for (int mi = 0; mi < MI; mi++) {
            int gi = wm * MI + mi;
            uint4 av = ASf4[gi * 32 + lane];
            const uint32_t* a = reinterpret_cast<const uint32_t*>(&av);
#pragma unroll
            for (int ni = 0; ni < 2; ni++) {
                uint32_t b[2] = {bfr[ni].x, bfr[ni].y};
                mma_f16(acc[mi][ni], a, b);
            }
        }
        __syncthreads();
    }

#pragma unroll
    for (int mi = 0; mi < MI; mi++) {
        int r0 = row0 + wm * (MI * 16) + mi * 16 + g;
        int r1 = r0 + 8;
        float sc0 = 1.f, sc1 = 1.f;
        if (SCALE) {
            if (r0 < M) sc0 = rowscale[r0];
            if (r1 < M) sc1 = rowscale[r1];
        }
#pragma unroll
        for (int ni = 0; ni < 2; ni++) {
            int c0 = col0 + wn * 16 + ni * 8 + tig * 2;
            if (c0 < N) {
                float2 bia = *reinterpret_cast<const float2*>(&bias[c0]);
                if (r0 < M) {
                    float vx = fmaxf(acc[mi][ni][0] + bia.x, 0.f) * sc0;
                    float vy = fmaxf(acc[mi][ni][1] + bia.y, 0.f) * sc0;
                    Ch[(size_t)r0 * strideC + (c0 >> 1)] = pack_h2(vx, vy);
                }
                if (r1 < M) {
                    float vx = fmaxf(acc[mi][ni][2] + bia.x, 0.f) * sc1;
                    float vy = fmaxf(acc[mi][ni][3] + bia.y, 0.f) * sc1;
                    Ch[(size_t)r1 * strideC + (c0 >> 1)] = pack_h2(vx, vy);
                }
            }
        }
    }
}

// ---------------- FC GEMM: split-bf16 A + W (R10 proven) ----------------
// OMODE: 0 = f32 float2, 1 = split-bf16 uint2
template <int MI, bool RELU, int OMODE>
__global__ __launch_bounds__(256) void gemm_bf16s(const uint2* __restrict__ A, int KP,
                                                  const uint4* __restrict__ BF, int NG,
                                                  const float* __restrict__ bias,
                                                  float* __restrict__ Cf,
                                                  uint2* __restrict__ Cs,
                                                  int M, int N, int K, int strideC) {
    constexpr int GI = 2 * MI;
    constexpr int BM = 16 * GI;
    constexpr int PLANE = GI * 128;
    __shared__ uint32_t ASw[2 * PLANE];
    const uint4* ASf4 = reinterpret_cast<const uint4*>(ASw);
    int tid = threadIdx.x;
    int warp = tid >> 5, lane = tid & 31;
    int g = lane >> 2, tig = lane & 3;
    int wm = warp >> 2, wn = warp & 3;
    int row0 = blockIdx.y * BM, col0 = blockIdx.x * 64;
    int chunks = (K + 15) >> 4;

    int li[MI], gbase[MI], colc[MI];
    bool rowok[MI];
#pragma unroll
    for (int j = 0; j < MI; j++) {
        int i = tid + j * 256;
        int m = i >> 3, c = i & 7;
        int gi = m >> 4;
        int fl = ((m & 7) << 2) | (c & 3);
        int reg = ((m >> 3) & 1) | ((c >> 2) << 1);
        li[j] = ((gi * 32 + fl) << 2) + reg;
        rowok[j] = (row0 + m) < M;
        gbase[j] = (row0 + m) * KP + c;
        colc[j] = c;
    }
    int ngBase = (col0 >> 3) + wn * 2;
    bool ngok0 = (ngBase < NG), ngok1 = (ngBase + 1 < NG);
    const uint4* BF0 = BF + (size_t)ngBase * 32 + lane;
    const uint4* BF1 = BF + (size_t)(ngBase + 1) * 32 + lane;

    float acc[MI][2][4];
#pragma unroll
    for (int a = 0; a < MI; a++)
#pragma unroll
        for (int b = 0; b < 2; b++)
#pragma unroll
            for (int c = 0; c < 4; c++) acc[a][b][c] = 0.f;

    for (int ch = 0; ch < chunks; ch++) {
        uint4 bfr[2];
        size_t bo = (size_t)ch * NG * 32;
        bfr[0] = ngok0 ? BF0[bo] : make_uint4(0, 0, 0, 0);
        bfr[1] = ngok1 ? BF1[bo] : make_uint4(0, 0, 0, 0);
        int gc = 8 * ch;
#pragma unroll
        for (int j = 0; j < MI; j++) {
            uint2 v = (rowok[j] && colc[j] + gc < KP) ? A[gbase[j] + gc] : make_uint2(0, 0);
            ASw[li[j]] = v.x;
            ASw[li[j] + PLANE] = v.y;
        }
        __syncthreads();
#pragma unroll
        for (int mi = 0; mi < MI; mi++) {
            int gi = wm * MI + mi;
            uint4 a0v = ASf4[gi * 32 + lane];
            uint4 a1v = ASf4[PLANE / 4 + gi * 32 + lane];
            const uint32_t* a0 = reinterpret_cast<const uint32_t*>(&a0v);
            const uint32_t* a1 = reinterpret_cast<const uint32_t*>(&a1v);
#pragma unroll
            for (int ni = 0; ni < 2; ni++) {
                uint32_t b0[2] = {bfr[ni].x, bfr[ni].y};
                uint32_t b1[2] = {bfr[ni].z, bfr[ni].w};
                mma_bf16(acc[mi][ni], a0, b0);
                mma_bf16(acc[mi][ni], a1, b0);
                mma_bf16(acc[mi][ni], a0, b1);
            }
        }
        __syncthreads();
    }

#pragma unroll
    for (int mi = 0; mi < MI; mi++) {
        int r0 = row0 + wm * (MI * 16) + mi * 16 + g;
        int r1 = r0 + 8;
#pragma unroll
        for (int ni = 0; ni < 2; ni++) {
            int c0 = col0 + wn * 16 + ni * 8 + tig * 2;
            if (c0 < N) {
                float2 bia = *reinterpret_cast<const float2*>(&bias[c0]);
                if (r0 < M) {
                    float vx = acc[mi][ni][0] + bia.x, vy = acc[mi][ni][1] + bia.y;
                    if (RELU) { vx = fmaxf(vx, 0.f); vy = fmaxf(vy, 0.f); }
                    if (OMODE == 1) Cs[(size_t)r0 * (N >> 1) + (c0 >> 1)] = split2(vx, vy);
                    else *reinterpret_cast<float2*>(&Cf[(size_t)r0 * strideC + c0]) = make_float2(vx, vy);
                }
                if (r1 < M) {
                    float vx = acc[mi][ni][2] + bia.x, vy = acc[mi][ni][3] + bia.y;
                    if (RELU) { vx = fmaxf(vx, 0.f); vy = fmaxf(vy, 0.f); }
                    if (OMODE == 1) Cs[(size_t)r1 * (N >> 1) + (c0 >> 1)] = split2(vx, vy);
                    else *reinterpret_cast<float2*>(&Cf[(size_t)r1 * strideC + c0]) = make_float2(vx, vy);
                }
            }
        }
    }
}

// ---------------- max pool over fp16 h3 (row stride 80 uint2 = 320 feats) -----------
__global__ void pool_kernel(const uint2* __restrict__ h2v, const int* __restrict__ batch,
                            uint2* __restrict__ pooledS) {
    __shared__ int sb[2];
    __shared__ float4 red[4][80];
    int lane = threadIdx.x, ty = threadIdx.y, gr = blockIdx.x;
    if (ty == 0 && lane < 2) {
        int target = gr + lane, lo = 0, hi = N_NODES;
        while (lo < hi) { int mid = (lo + hi) >> 1; if (batch[mid] < target) lo = mid + 1; else hi = mid; }
        sb[lane] = lo;
    }
    __syncthreads();
    int beg = sb[0], end = sb[1];
    const int DQ = D3 / 4;
    float4 m = make_float4(0.f, 0.f, 0.f, 0.f);
    if (lane < DQ) {
        for (int node = beg + ty; node < end; node += 4) {
            float4 v = h2x2_to_f4(h2v[(size_t)node * 80 + lane]);
            m.x = fmaxf(m.x, v.x); m.y = fmaxf(m.y, v.y);
            m.z = fmaxf(m.z, v.z); m.w = fmaxf(m.w, v.w);
        }
    }
    red[ty][lane] = m;
    __syncthreads();
    if (ty == 0 && lane < DQ) {
        float4 a = red[0][lane], b = red[1][lane], c = red[2][lane], d = red[3][lane];
        float4 r;
        r.x = fmaxf(fmaxf(a.x, b.x), fmaxf(c.x, d.x));
        r.y = fmaxf(fmaxf(a.y, b.y), fmaxf(c.y, d.y));
        r.z = fmaxf(fmaxf(a.z, b.z), fmaxf(c.z, d.z));
        r.w = fmaxf(fmaxf(a.w, b.w), fmaxf(c.w, d.w));
        pooledS[(size_t)gr * (D3 / 2) + 2 * lane]     = split2(r.x, r.y);
        pooledS[(size_t)gr * (D3 / 2) + 2 * lane + 1] = split2(r.z, r.w);
    }
}

// ---------------- launch ----------------
extern "C" void kernel_launch(void* const* d_in, const int* in_sizes, int n_in,
                              void* d_out, int out_size) {
    const float* x     = (const float*)d_in[0];
    const int*   ei    = (const int*)d_in[1];
    const int*   batch = (const int*)d_in[2];
    const float* W1 = (const float*)d_in[3];  const float* b1  = (const float*)d_in[4];
    const float* W2 = (const float*)d_in[5];  const float* b2  = (const float*)d_in[6];
    const float* W3 = (const float*)d_in[7];  const float* b3  = (const float*)d_in[8];
    const float* Wf1 = (const float*)d_in[9]; const float* bf1 = (const float*)d_in[10];
    const float* Wf2 = (const float*)d_in[11];const float* bf2 = (const float*)d_in[12];
    float* out = (float*)d_out;

    const int* src = ei;
    const int* dst = ei + N_EDGES;

    int *cnt, *off, *csr, *bsum;
    float *dinv;
    uint2 *yh, *pooledS, *fc1S, *wfh;
    uint32_t *sA;
    uint4 *wf;
    cudaGetSymbolAddress((void**)&cnt, g_cnt);
    cudaGetSymbolAddress((void**)&off, g_off);
    cudaGetSymbolAddress((void**)&csr, g_csr);
    cudaGetSymbolAddress((void**)&bsum, g_bsum);
    cudaGetSymbolAddress((void**)&dinv, g_dinv);
    cudaGetSymbolAddress((void**)&yh, g_yh);
    cudaGetSymbolAddress((void**)&sA, g_sA);
    cudaGetSymbolAddress((void**)&pooledS, g_pooledS);
    cudaGetSymbolAddress((void**)&fc1S, g_fc1S);
    cudaGetSymbolAddress((void**)&wfh, g_wfragh);
    cudaGetSymbolAddress((void**)&wf, g_wfrag);
    uint32_t* yhu = (uint32_t*)yh;

    // ---- fused zero(cnt) + weight fragment conversion ----
    conv_all<<<(4124 + 7) / 8, 256>>>(W1, W2, W3, Wf1, Wf2, wfh, wf, (int4*)cnt);

    // ---- CSR build + y0 = fp16(dinv*x), stride 40 uint ----
    count_deg<<<(N_EDGES / 2 + 255) / 256, 256>>>((const int2*)dst, cnt, N_EDGES / 2);
    scan1<<<SCAN_BLOCKS, 1024>>>(cnt, off, dinv, bsum);
    scan_add<<<SCAN_BLOCKS, 1024>>>(off, bsum);
    scatter_scale<<<(N_EDGES + 255) / 256, 256>>>(src, dst, off, cnt, csr, dinv,
                                                  (const float2*)x, yhu);

    const int RB256 = (N_NODES + 255) / 256;  // 118

    // ---- layer 1: y1 = fp16(dinv*relu(agg(y0)@W1+b1)), stride 40 uint ----
    aggregate_h2<20, 20, 39><<<(N_NODES + 11) / 12, dim3(20, 12)>>>(yh, off, csr, dinv, sA);
    gemm_f16a<8, true><<<dim3(2, RB256), 256>>>(
        sA, 39, wfh + WH_OFF1, 10, b1, dinv, yhu, N_NODES, D1, 40);

    // ---- layer 2: y2 stride 80 uint ----
    aggregate_h2<20, 20, 39><<<(N_NODES + 11) / 12, dim3(20, 12)>>>(yh, off, csr, dinv, sA);
    gemm_f16a<8, true><<<dim3(3, RB256), 256>>>(
        sA, 39, wfh + WH_OFF2, 20, b2, dinv, yhu, N_NODES, D2, 80);

    // ---- layer 3: h3 stride 160 uint (unscaled, feeds pooling) ----
    aggregate_h2<40, 40, 78><<<(N_NODES + 5) / 6, dim3(40, 6)>>>(yh, off, csr, dinv, sA);
    gemm_f16a<8, false><<<dim3(5, RB256), 256>>>(
        sA, 78, wfh + WH_OFF3, 39, b3, nullptr, yhu, N_NODES, D3, 160);

    // ---- pool ----
    pool_kernel<<<N_GRAPHS, dim3(80, 4)>>>(yh, batch, pooledS);

    // ---- FC head (split-bf16 fp32-accurate path, unchanged) ----
    gemm_bf16s<4, true, 1><<<dim3(16, (N_GRAPHS + 127) / 128), 256>>>(
        pooledS, D3 / 2, wf + WF_OFFF1, 128, bf1, nullptr, fc1S, N_GRAPHS, 1024, D3, 0);
    gemm_bf16s<4, false, 0><<<dim3(2, (N_GRAPHS + 127) / 128), 256>>>(
        fc1S, 512, wf + WF_OFFF2, 16, bf2, out, nullptr, N_GRAPHS, 128, 1024, 128);
}

// round 17
// speedup vs baseline: 1.5953x; 1.0838x over previous
#include <cuda_runtime.h>
#include <cuda_bf16.h>
#include <cuda_fp16.h>
#include <cstdint>

#define N_NODES  30000
#define N_EDGES  480000
#define N_GRAPHS 500
#define D1 78
#define D2 156
#define D3 312
#define SCAN_BLOCKS 30   // ceil(30000/1024)

// ---------------- scratch ----------------
__device__ int   g_cnt[N_NODES];
__device__ int   g_off[N_NODES + 1];
__device__ int   g_bsum[SCAN_BLOCKS];
__device__ int   g_csr[N_EDGES];
__device__ float g_dinv[N_NODES];
__device__ uint2 g_yh[(size_t)N_NODES * 80];         // fp16 activations (half2-packed, padded)
__device__ uint32_t g_sA[(size_t)N_NODES * D1];      // fp16 GEMM A (pairs; max 78/row)
__device__ uint32_t g_pooledH[N_GRAPHS * (D3 / 2)];  // fp16 pooled (exact: max of fp16)
__device__ uint32_t g_fc1H[N_GRAPHS * 512];          // fp16 fc1 activations
// node-layer weight fragments: plain fp16, uint2 per (chunk,ng,lane)
#define WH_OFF1 0
#define WH_OFF2 1600      // 5*10*32
#define WH_OFF3 4800      // +5*20*32
#define WH_TOTAL 17280    // +10*39*32
__device__ uint2 g_wfragh[WH_TOTAL];
// FC weight fragments: split-fp16, uint4 per (chunk,ng,lane)
#define WF_OFFF1 0
#define WF_OFFF2 81920    // 20*128*32
#define WF_TOTAL 114688   // +64*16*32
__device__ uint4 g_wfrag[WF_TOTAL];

// ---------------- helpers ----------------
__device__ __forceinline__ uint32_t pack_h2(float a, float b) {
    __half2 h = __floats2half2_rn(a, b);
    return *reinterpret_cast<uint32_t*>(&h);
}
__device__ __forceinline__ uint2 split2h(float x, float y) {     // split-fp16 (FC W path)
    uint32_t s0 = pack_h2(x, y);
    float2 f = __half22float2(*reinterpret_cast<__half2*>(&s0));
    uint32_t s1 = pack_h2(x - f.x, y - f.y);
    return make_uint2(s0, s1);
}
__device__ __forceinline__ float4 h2x2_to_f4(uint2 u) {
    float2 a = __half22float2(*reinterpret_cast<__half2*>(&u.x));
    float2 b = __half22float2(*reinterpret_cast<__half2*>(&u.y));
    return make_float4(a.x, a.y, b.x, b.y);
}

__device__ __forceinline__ void mma_f16(float* c, const uint32_t* a, const uint32_t* b) {
    asm volatile(
        "mma.sync.aligned.m16n8k16.row.col.f32.f16.f16.f32 "
        "{%0,%1,%2,%3}, {%4,%5,%6,%7}, {%8,%9}, {%0,%1,%2,%3};\n"
        : "+f"(c[0]), "+f"(c[1]), "+f"(c[2]), "+f"(c[3])
        : "r"(a[0]), "r"(a[1]), "r"(a[2]), "r"(a[3]), "r"(b[0]), "r"(b[1]));
}

// ---------------- CSR build ----------------
__global__ void count_deg(const int2* __restrict__ dst2, int* __restrict__ cnt, int e2) {
    int i = blockIdx.x * blockDim.x + threadIdx.x;
    if (i < e2) {
        int2 d = dst2[i];
        atomicAdd(&cnt[d.x], 1);
        atomicAdd(&cnt[d.y], 1);
    }
}

__global__ void scan1(const int* __restrict__ cnt, int* __restrict__ off,
                      float* __restrict__ dinv, int* __restrict__ bsum) {
    __shared__ int sm[1024];
    int tid = threadIdx.x;
    int i = blockIdx.x * 1024 + tid;
    int c = (i < N_NODES) ? cnt[i] : 0;
    if (i < N_NODES) dinv[i] = rsqrtf((float)c + 1.0f);
    sm[tid] = c;
    __syncthreads();
    for (int d = 1; d < 1024; d <<= 1) {
        int t = (tid >= d) ? sm[tid - d] : 0;
        __syncthreads();
        sm[tid] += t;
        __syncthreads();
    }
    if (i < N_NODES) off[i] = sm[tid] - c;
    if (tid == 1023) bsum[blockIdx.x] = sm[1023];
}

__global__ void scan_add(int* __restrict__ off, const int* __restrict__ bsum) {
    __shared__ int pre[32];
    int tid = threadIdx.x;
    if (tid < 32) {
        int v = (tid < SCAN_BLOCKS) ? bsum[tid] : 0;
#pragma unroll
        for (int d = 1; d < 32; d <<= 1) {
            int t = __shfl_up_sync(0xffffffffu, v, d);
            if (tid >= d) v += t;
        }
        pre[tid] = v;
    }
    __syncthreads();
    int b = blockIdx.x;
    int add = (b == 0) ? 0 : pre[b - 1];
    int i = b * 1024 + tid;
    if (i < N_NODES && b > 0) off[i] += add;
    if (b == 0 && tid == 0) off[N_NODES] = N_EDGES;
}

// scatter edges (consumes cnt) + y0 = fp16(dinv * x), row stride 40 uint (80 feats)
__global__ void scatter_scale(const int* __restrict__ src, const int* __restrict__ dst,
                              const int* __restrict__ off, int* __restrict__ cnt,
                              int* __restrict__ csr, const float* __restrict__ dinv,
                              const float2* __restrict__ x2, uint32_t* __restrict__ yh) {
    int t = blockIdx.x * blockDim.x + threadIdx.x;
    if (t < N_EDGES) {
        int d = dst[t];
        int pos = off[d] + atomicSub(&cnt[d], 1) - 1;
        csr[pos] = src[t];
    }
    const int DP = D1 / 2;  // 39 pairs
    int total = N_NODES * DP;
    int stride = gridDim.x * blockDim.x;
    for (int i = t; i < total; i += stride) {
        int node = i / DP;
        int f = i - node * DP;
        float2 v = x2[i];
        float di = dinv[node];
        yh[node * 40 + f] = pack_h2(di * v.x, di * v.y);
    }
}

// ---------------- fused: zero cnt + weight -> fragment conversion ----------------
__global__ void conv_all(const float* __restrict__ W1, const float* __restrict__ W2,
                         const float* __restrict__ W3, const float* __restrict__ Wf1,
                         const float* __restrict__ Wf2,
                         uint2* __restrict__ outh, uint4* __restrict__ out,
                         int4* __restrict__ cnt4) {
    int zi = blockIdx.x * 256 + threadIdx.x;
    if (zi < N_NODES / 4) cnt4[zi] = make_int4(0, 0, 0, 0);

    int unit = blockIdx.x * 8 + (threadIdx.x >> 5);
    int lane = threadIdx.x & 31;
    const float* W; int K, N, NG, base, u;
    bool h16;
    if (unit < 50)        { W = W1;  K = 78;   N = 78;   NG = 10;  base = WH_OFF1;  u = unit;        h16 = true; }
    else if (unit < 150)  { W = W2;  K = 78;   N = 156;  NG = 20;  base = WH_OFF2;  u = unit - 50;   h16 = true; }
    else if (unit < 540)  { W = W3;  K = 156;  N = 312;  NG = 39;  base = WH_OFF3;  u = unit - 150;  h16 = true; }
    else if (unit < 3100) { W = Wf1; K = 312;  N = 1024; NG = 128; base = WF_OFFF1; u = unit - 540;  h16 = false; }
    else if (unit < 4124) { W = Wf2; K = 1024; N = 128;  NG = 16;  base = WF_OFFF2; u = unit - 3100; h16 = false; }
    else return;
    int chunk = u / NG, ng = u % NG;
    int n = ng * 8 + (lane >> 2);
    int k0 = chunk * 16 + 2 * (lane & 3);
    float f[4];
#pragma unroll
    for (int j = 0; j < 4; j++) {
        int k = k0 + (j >> 1) * 8 + (j & 1);
        f[j] = (k < K && n < N) ? W[(size_t)k * N + n] : 0.f;
    }
    if (h16) {
        outh[base + (size_t)u * 32 + lane] = make_uint2(pack_h2(f[0], f[1]), pack_h2(f[2], f[3]));
    } else {
        uint2 p0 = split2h(f[0], f[1]);
        uint2 p1 = split2h(f[2], f[3]);
        out[base + (size_t)u * 32 + lane] = make_uint4(p0.x, p1.x, p0.y, p1.y);
    }
}

// ---------------- aggregation over fp16 y, fp32 accumulate, fp16 out ----------
template <int Q, int QS, int P>
__global__ void aggregate_h2(const uint2* __restrict__ y2, const int* __restrict__ off,
                             const int* __restrict__ csr, const float* __restrict__ dinv,
                             uint32_t* __restrict__ outA) {
    int node = blockIdx.x * blockDim.y + threadIdx.y;
    if (node >= N_NODES) return;
    int f = threadIdx.x;
    int beg = off[node], end = off[node + 1];
    const uint2* yb = y2 + f;
    float4 acc = h2x2_to_f4(yb[(size_t)node * QS]);
    int e = beg;
    for (; e + 4 <= end; e += 4) {
        int s0 = csr[e], s1 = csr[e + 1], s2 = csr[e + 2], s3 = csr[e + 3];
        float4 v0 = h2x2_to_f4(yb[(size_t)s0 * QS]);
        float4 v1 = h2x2_to_f4(yb[(size_t)s1 * QS]);
        float4 v2 = h2x2_to_f4(yb[(size_t)s2 * QS]);
        float4 v3 = h2x2_to_f4(yb[(size_t)s3 * QS]);
        acc.x += (v0.x + v1.x) + (v2.x + v3.x);
        acc.y += (v0.y + v1.y) + (v2.y + v3.y);
        acc.z += (v0.z + v1.z) + (v2.z + v3.z);
        acc.w += (v0.w + v1.w) + (v2.w + v3.w);
    }
    for (; e < end; e++) {
        int s = csr[e];
        float4 v = h2x2_to_f4(yb[(size_t)s * QS]);
        acc.x += v.x; acc.y += v.y; acc.z += v.z; acc.w += v.w;
    }
    float di = dinv[node];
    if (2 * f < P)
        outA[(size_t)node * P + 2 * f] = pack_h2(di * acc.x, di * acc.y);
    if (2 * f + 1 < P)
        outA[(size_t)node * P + 2 * f + 1] = pack_h2(di * acc.z, di * acc.w);
}

// ---------------- node GEMM: fp16 A x fp16 W, 1 mma/step (R16 proven) ----------
template <int MI, bool SCALE>
__global__ __launch_bounds__(256) void gemm_f16a(const uint32_t* __restrict__ A, int KP,
                                                 const uint2* __restrict__ BF, int NG,
                                                 const float* __restrict__ bias,
                                                 const float* __restrict__ rowscale,
                                                 uint32_t* __restrict__ Ch,
                                                 int M, int N, int strideC) {
    constexpr int GI = 2 * MI;
    constexpr int PLANE = GI * 128;
    __shared__ uint32_t ASw[PLANE];
    const uint4* ASf4 = reinterpret_cast<const uint4*>(ASw);
    int tid = threadIdx.x;
    int warp = tid >> 5, lane = tid & 31;
    int g = lane >> 2, tig = lane & 3;
    int wm = warp >> 2, wn = warp & 3;
    int row0 = blockIdx.y * (16 * GI), col0 = blockIdx.x * 64;
    int chunks = (2 * KP + 15) >> 4;

    int li[MI], gbase[MI], colc[MI];
    bool rowok[MI];
#pragma unroll
    for (int j = 0; j < MI; j++) {
        int i = tid + j * 256;
        int m = i >> 3, c = i & 7;
        int gi = m >> 4;
        int fl = ((m & 7) << 2) | (c & 3);
        int reg = ((m >> 3) & 1) | ((c >> 2) << 1);
        li[j] = ((gi * 32 + fl) << 2) + reg;
        rowok[j] = (row0 + m) < M;
        gbase[j] = (row0 + m) * KP + c;
        colc[j] = c;
    }
    int ngBase = (col0 >> 3) + wn * 2;
    bool ngok0 = (ngBase < NG), ngok1 = (ngBase + 1 < NG);
    const uint2* BF0 = BF + (size_t)ngBase * 32 + lane;
    const uint2* BF1 = BF + (size_t)(ngBase + 1) * 32 + lane;

    float acc[MI][2][4];
#pragma unroll
    for (int a = 0; a < MI; a++)
#pragma unroll
        for (int b = 0; b < 2; b++)
#pragma unroll
            for (int c = 0; c < 4; c++) acc[a][b][c] = 0.f;

    for (int ch = 0; ch < chunks; ch++) {
        uint2 bfr[2];
        size_t bo = (size_t)ch * NG * 32;
        bfr[0] = ngok0 ? BF0[bo] : make_uint2(0, 0);
        bfr[1] = ngok1 ? BF1[bo] : make_uint2(0, 0);
        int gc = 8 * ch;
#pragma unroll
        for (int j = 0; j < MI; j++) {
            uint32_t v = (rowok[j] && colc[j] + gc < KP) ? A[gbase[j] + gc] : 0u;
            ASw[li[j]] = v;
        }
        __syncthreads();

#pragma unroll
        for (int mi = 0; mi < MI; mi++) {
            int gi = wm * MI + mi;
            uint4 av = ASf4[gi * 32 + lane];
            const uint32_t* a = reinterpret_cast<const uint32_t*>(&av);
#pragma unroll
            for (int ni = 0; ni < 2; ni++) {
                uint32_t b[2] = {bfr[ni].x, bfr[ni].y};
                mma_f16(acc[mi][ni], a, b);
            }
        }
        __syncthreads();
    }

#pragma unroll
    for (int mi = 0; mi < MI; mi++) {
        int r0 = row0 + wm * (MI * 16) + mi * 16 + g;
        int r1 = r0 + 8;
        float sc0 = 1.f, sc1 = 1.f;
        if (SCALE) {
            if (r0 < M) sc0 = rowscale[r0];
            if (r1 < M) sc1 = rowscale[r1];
        }
#pragma unroll
        for (int ni = 0; ni < 2; ni++) {
            int c0 = col0 + wn * 16 + ni * 8 + tig * 2;
            if (c0 < N) {
                float2 bia = *reinterpret_cast<const float2*>(&bias[c0]);
                if (r0 < M) {
                    float vx = fmaxf(acc[mi][ni][0] + bia.x, 0.f) * sc0;
                    float vy = fmaxf(acc[mi][ni][1] + bia.y, 0.f) * sc0;
                    Ch[(size_t)r0 * strideC + (c0 >> 1)] = pack_h2(vx, vy);
                }
                if (r1 < M) {
                    float vx = fmaxf(acc[mi][ni][2] + bia.x, 0.f) * sc1;
                    float vy = fmaxf(acc[mi][ni][3] + bia.y, 0.f) * sc1;
                    Ch[(size_t)r1 * strideC + (c0 >> 1)] = pack_h2(vx, vy);
                }
            }
        }
    }
}

// ---------------- FC GEMM: fp16 A x split-fp16 W (2 mma), OMODE 0=f32 / 2=fp16 ------
template <int MI, bool RELU, int OMODE>
__global__ __launch_bounds__(256) void gemm_f16w2(const uint32_t* __restrict__ A, int KP,
                                                  const uint4* __restrict__ BF, int NG,
                                                  const float* __restrict__ bias,
                                                  float* __restrict__ Cf,
                                                  uint32_t* __restrict__ Ch,
                                                  int M, int N, int strideC) {
    constexpr int GI = 2 * MI;
    constexpr int PLANE = GI * 128;
    __shared__ uint32_t ASw[PLANE];
    const uint4* ASf4 = reinterpret_cast<const uint4*>(ASw);
    int tid = threadIdx.x;
    int warp = tid >> 5, lane = tid & 31;
    int g = lane >> 2, tig = lane & 3;
    int wm = warp >> 2, wn = warp & 3;
    int row0 = blockIdx.y * (16 * GI), col0 = blockIdx.x * 64;
    int chunks = (2 * KP + 15) >> 4;

    int li[MI], gbase[MI], colc[MI];
    bool rowok[MI];
#pragma unroll
    for (int j = 0; j < MI; j++) {
        int i = tid + j * 256;
        int m = i >> 3, c = i & 7;
        int gi = m >> 4;
        int fl = ((m & 7) << 2) | (c & 3);
        int reg = ((m >> 3) & 1) | ((c >> 2) << 1);
        li[j] = ((gi * 32 + fl) << 2) + reg;
        rowok[j] = (row0 + m) < M;
        gbase[j] = (row0 + m) * KP + c;
        colc[j] = c;
    }
    int ngBase = (col0 >> 3) + wn * 2;
    bool ngok0 = (ngBase < NG), ngok1 = (ngBase + 1 < NG);
    const uint4* BF0 = BF + (size_t)ngBase * 32 + lane;
    const uint4* BF1 = BF + (size_t)(ngBase + 1) * 32 + lane;

    float acc[MI][2][4];
#pragma unroll
    for (int a = 0; a < MI; a++)
#pragma unroll
        for (int b = 0; b < 2; b++)
#pragma unroll
            for (int c = 0; c < 4; c++) acc[a][b][c] = 0.f;

    for (int ch = 0; ch < chunks; ch++) {
        uint4 bfr[2];
        size_t bo = (size_t)ch * NG * 32;
        bfr[0] = ngok0 ? BF0[bo] : make_uint4(0, 0, 0, 0);
        bfr[1] = ngok1 ? BF1[bo] : make_uint4(0, 0, 0, 0);
        int gc = 8 * ch;
#pragma unroll
        for (int j = 0; j < MI; j++) {
            uint32_t v = (rowok[j] && colc[j] + gc < KP) ? A[gbase[j] + gc] : 0u;
            ASw[li[j]] = v;
        }
        __syncthreads();

#pragma unroll
        for (int mi = 0; mi < MI; mi++) {
            int gi = wm * MI + mi;
            uint4 av = ASf4[gi * 32 + lane];
            const uint32_t* a = reinterpret_cast<const uint32_t*>(&av);
#pragma unroll
            for (int ni = 0; ni < 2; ni++) {
                uint32_t b0[2] = {bfr[ni].x, bfr[ni].y};
                uint32_t b1[2] = {bfr[ni].z, bfr[ni].w};
                mma_f16(acc[mi][ni], a, b0);   // A * Whi
                mma_f16(acc[mi][ni], a, b1);   // A * Wlo
            }
        }
        __syncthreads();
    }

#pragma unroll
    for (int mi = 0; mi < MI; mi++) {
        int r0 = row0 + wm * (MI * 16) + mi * 16 + g;
        int r1 = r0 + 8;
#pragma unroll
        for (int ni = 0; ni < 2; ni++) {
            int c0 = col0 + wn * 16 + ni * 8 + tig * 2;
            if (c0 < N) {
                float2 bia = *reinterpret_cast<const float2*>(&bias[c0]);
                if (r0 < M) {
                    float vx = acc[mi][ni][0] + bia.x, vy = acc[mi][ni][1] + bia.y;
                    if (RELU) { vx = fmaxf(vx, 0.f); vy = fmaxf(vy, 0.f); }
                    if (OMODE == 2) Ch[(size_t)r0 * strideC + (c0 >> 1)] = pack_h2(vx, vy);
                    else *reinterpret_cast<float2*>(&Cf[(size_t)r0 * strideC + c0]) = make_float2(vx, vy);
                }
                if (r1 < M) {
                    float vx = acc[mi][ni][2] + bia.x, vy = acc[mi][ni][3] + bia.y;
                    if (RELU) { vx = fmaxf(vx, 0.f); vy = fmaxf(vy, 0.f); }
                    if (OMODE == 2) Ch[(size_t)r1 * strideC + (c0 >> 1)] = pack_h2(vx, vy);
                    else *reinterpret_cast<float2*>(&Cf[(size_t)r1 * strideC + c0]) = make_float2(vx, vy);
                }
            }
        }
    }
}

// ---------------- max pool over fp16 h3 -> fp16 pooled (exact) ----------------
__global__ void pool_kernel(const uint2* __restrict__ h2v, const int* __restrict__ batch,
                            uint32_t* __restrict__ pooledH) {
    __shared__ int sb[2];
    __shared__ float4 red[4][80];
    int lane = threadIdx.x, ty = threadIdx.y, gr = blockIdx.x;
    if (ty == 0 && lane < 2) {
        int target = gr + lane, lo = 0, hi = N_NODES;
        while (lo < hi) { int mid = (lo + hi) >> 1; if (batch[mid] < target) lo = mid + 1; else hi = mid; }
        sb[lane] = lo;
    }
    __syncthreads();
    int beg = sb[0], end = sb[1];
    const int DQ = D3 / 4;
    float4 m = make_float4(0.f, 0.f, 0.f, 0.f);
    if (lane < DQ) {
        for (int node = beg + ty; node < end; node += 4) {
            float4 v = h2x2_to_f4(h2v[(size_t)node * 80 + lane]);
            m.x = fmaxf(m.x, v.x); m.y = fmaxf(m.y, v.y);
            m.z = fmaxf(m.z, v.z); m.w = fmaxf(m.w, v.w);
        }
    }
    red[ty][lane] = m;
    __syncthreads();
    if (ty == 0 && lane < DQ) {
        float4 a = red[0][lane], b = red[1][lane], c = red[2][lane], d = red[3][lane];
        float4 r;
        r.x = fmaxf(fmaxf(a.x, b.x), fmaxf(c.x, d.x));
        r.y = fmaxf(fmaxf(a.y, b.y), fmaxf(c.y, d.y));
        r.z = fmaxf(fmaxf(a.z, b.z), fmaxf(c.z, d.z));
        r.w = fmaxf(fmaxf(a.w, b.w), fmaxf(c.w, d.w));
        pooledH[(size_t)gr * (D3 / 2) + 2 * lane]     = pack_h2(r.x, r.y);
        pooledH[(size_t)gr * (D3 / 2) + 2 * lane + 1] = pack_h2(r.z, r.w);
    }
}

// ---------------- launch ----------------
extern "C" void kernel_launch(void* const* d_in, const int* in_sizes, int n_in,
                              void* d_out, int out_size) {
    const float* x     = (const float*)d_in[0];
    const int*   ei    = (const int*)d_in[1];
    const int*   batch = (const int*)d_in[2];
    const float* W1 = (const float*)d_in[3];  const float* b1  = (const float*)d_in[4];
    const float* W2 = (const float*)d_in[5];  const float* b2  = (const float*)d_in[6];
    const float* W3 = (const float*)d_in[7];  const float* b3  = (const float*)d_in[8];
    const float* Wf1 = (const float*)d_in[9]; const float* bf1 = (const float*)d_in[10];
    const float* Wf2 = (const float*)d_in[11];const float* bf2 = (const float*)d_in[12];
    float* out = (float*)d_out;

    const int* src = ei;
    const int* dst = ei + N_EDGES;

    int *cnt, *off, *csr, *bsum;
    float *dinv;
    uint2 *yh, *wfh;
    uint32_t *sA, *pooledH, *fc1H;
    uint4 *wf;
    cudaGetSymbolAddress((void**)&cnt, g_cnt);
    cudaGetSymbolAddress((void**)&off, g_off);
    cudaGetSymbolAddress((void**)&csr, g_csr);
    cudaGetSymbolAddress((void**)&bsum, g_bsum);
    cudaGetSymbolAddress((void**)&dinv, g_dinv);
    cudaGetSymbolAddress((void**)&yh, g_yh);
    cudaGetSymbolAddress((void**)&sA, g_sA);
    cudaGetSymbolAddress((void**)&pooledH, g_pooledH);
    cudaGetSymbolAddress((void**)&fc1H, g_fc1H);
    cudaGetSymbolAddress((void**)&wfh, g_wfragh);
    cudaGetSymbolAddress((void**)&wf, g_wfrag);
    uint32_t* yhu = (uint32_t*)yh;

    // ---- fused zero(cnt) + weight fragment conversion ----
    conv_all<<<(4124 + 7) / 8, 256>>>(W1, W2, W3, Wf1, Wf2, wfh, wf, (int4*)cnt);

    // ---- CSR build + y0 = fp16(dinv*x), stride 40 uint ----
    count_deg<<<(N_EDGES / 2 + 255) / 256, 256>>>((const int2*)dst, cnt, N_EDGES / 2);
    scan1<<<SCAN_BLOCKS, 1024>>>(cnt, off, dinv, bsum);
    scan_add<<<SCAN_BLOCKS, 1024>>>(off, bsum);
    scatter_scale<<<(N_EDGES + 255) / 256, 256>>>(src, dst, off, cnt, csr, dinv,
                                                  (const float2*)x, yhu);

    const int RB256 = (N_NODES + 255) / 256;  // 118

    // ---- layer 1: y1 = fp16(dinv*relu(agg(y0)@W1+b1)), stride 40 uint ----
    aggregate_h2<20, 20, 39><<<(N_NODES + 11) / 12, dim3(20, 12)>>>(yh, off, csr, dinv, sA);
    gemm_f16a<8, true><<<dim3(2, RB256), 256>>>(
        sA, 39, wfh + WH_OFF1, 10, b1, dinv, yhu, N_NODES, D1, 40);

    // ---- layer 2: y2 stride 80 uint ----
    aggregate_h2<20, 20, 39><<<(N_NODES + 11) / 12, dim3(20, 12)>>>(yh, off, csr, dinv, sA);
    gemm_f16a<8, true><<<dim3(3, RB256), 256>>>(
        sA, 39, wfh + WH_OFF2, 20, b2, dinv, yhu, N_NODES, D2, 80);

    // ---- layer 3: h3 stride 160 uint (unscaled, feeds pooling) ----
    aggregate_h2<40, 40, 78><<<(N_NODES + 5) / 6, dim3(40, 6)>>>(yh, off, csr, dinv, sA);
    gemm_f16a<8, false><<<dim3(5, RB256), 256>>>(
        sA, 78, wfh + WH_OFF3, 39, b3, nullptr, yhu, N_NODES, D3, 160);

    // ---- pool (fp16 out, exact) ----
    pool_kernel<<<N_GRAPHS, dim3(80, 4)>>>(yh, batch, pooledH);

    // ---- FC head: fp16 A x split-fp16 W (2 mma) ----
    gemm_f16w2<4, true, 2><<<dim3(16, (N_GRAPHS + 127) / 128), 256>>>(
        pooledH, D3 / 2, wf + WF_OFFF1, 128, bf1, nullptr, fc1H, N_GRAPHS, 1024, 512);
    gemm_f16w2<4, false, 0><<<dim3(2, (N_GRAPHS + 127) / 128), 256>>>(
        fc1H, 512, wf + WF_OFFF2, 16, bf2, out, nullptr, N_GRAPHS, 128, 128);
}